// round 10
// baseline (speedup 1.0000x reference)
#include <cuda_runtime.h>
#include <cuda_bf16.h>
#include <math.h>
#include <stdint.h>

// Problem shape (fixed by the dataset)
#define BB   2
#define NN   1024
#define LLEN 4096
#define CDIM 1024
#define HH   16
#define DD   64

// ---------------- scratch (device globals; no allocs allowed) ---------------
__device__ __nv_bfloat16 g_xh[BB * NN * CDIM],   g_xl[BB * NN * CDIM];
__device__ __nv_bfloat16 g_yh[BB * LLEN * CDIM], g_yl[BB * LLEN * CDIM];
__device__ __nv_bfloat16 g_wh[4 * CDIM * CDIM],  g_wl[4 * CDIM * CDIM];
__device__ __nv_bfloat16 g_qh[BB * NN * CDIM],   g_ql[BB * NN * CDIM];   // pre-scaled by 0.125
__device__ __nv_bfloat16 g_kh[BB * LLEN * CDIM], g_kl[BB * LLEN * CDIM];
__device__ __nv_bfloat16 g_vh[BB * LLEN * CDIM], g_vl[BB * LLEN * CDIM];
__device__ __nv_bfloat16 g_aoh[BB * NN * CDIM],  g_aol[BB * NN * CDIM];
__device__ float g_po[2][BB * NN * CDIM];        // split-K partials (16 MB)

extern __shared__ char dsm[];

// ---------------------------------------------------------------------------
// helpers
// ---------------------------------------------------------------------------
static __device__ __forceinline__ uint32_t smem_u32(const void* p) {
    uint32_t a;
    asm("{ .reg .u64 t; cvta.to.shared.u64 t, %1; cvt.u32.u64 %0, t; }"
        : "=r"(a) : "l"(p));
    return a;
}
static __device__ __forceinline__ void cp16(uint32_t dst, const void* src) {
    asm volatile("cp.async.cg.shared.global [%0], [%1], 16;"
                 :: "r"(dst), "l"(src));
}
static __device__ __forceinline__ void cp_commit() {
    asm volatile("cp.async.commit_group;" ::: "memory");
}
template <int N_>
static __device__ __forceinline__ void cp_wait() {
    asm volatile("cp.async.wait_group %0;" :: "n"(N_) : "memory");
}
static __device__ __forceinline__ void mma_bf16(
    float* c, uint32_t a0, uint32_t a1, uint32_t a2, uint32_t a3,
    uint32_t b0, uint32_t b1)
{
    asm volatile(
        "mma.sync.aligned.m16n8k16.row.col.f32.bf16.bf16.f32 "
        "{%0,%1,%2,%3}, {%4,%5,%6,%7}, {%8,%9}, {%0,%1,%2,%3};"
        : "+f"(c[0]), "+f"(c[1]), "+f"(c[2]), "+f"(c[3])
        : "r"(a0), "r"(a1), "r"(a2), "r"(a3), "r"(b0), "r"(b1));
}
static __device__ __forceinline__ void ldsm_x4(uint32_t* r, uint32_t addr) {
    asm volatile("ldmatrix.sync.aligned.m8n8.x4.shared.b16 {%0,%1,%2,%3}, [%4];"
                 : "=r"(r[0]), "=r"(r[1]), "=r"(r[2]), "=r"(r[3]) : "r"(addr));
}
static __device__ __forceinline__ void ldsm_x2_t(uint32_t& r0, uint32_t& r1, uint32_t addr) {
    asm volatile("ldmatrix.sync.aligned.m8n8.x2.trans.shared.b16 {%0,%1}, [%2];"
                 : "=r"(r0), "=r"(r1) : "r"(addr));
}
static __device__ __forceinline__ void pack_hl(
    float a, float b, uint32_t& hi, uint32_t& lo)
{
    __nv_bfloat162 h = __floats2bfloat162_rn(a, b);
    __nv_bfloat162 l = __floats2bfloat162_rn(a - __bfloat162float(h.x),
                                             b - __bfloat162float(h.y));
    hi = *(uint32_t*)&h;
    lo = *(uint32_t*)&l;
}

// ---------------------------------------------------------------------------
// fused split: all six fp32 tensors -> bf16 hi/lo in ONE launch
// ---------------------------------------------------------------------------
#define X4 ((BB * NN * CDIM) / 4)
#define Y4 ((BB * LLEN * CDIM) / 4)
#define W4 ((CDIM * CDIM) / 4)
#define TOT4 (X4 + Y4 + 4 * W4)

__global__ void split_all(const float* __restrict__ x, const float* __restrict__ y,
                          const float* __restrict__ Wq, const float* __restrict__ Wk,
                          const float* __restrict__ Wv, const float* __restrict__ Wp,
                          __nv_bfloat16* __restrict__ xh, __nv_bfloat16* __restrict__ xl,
                          __nv_bfloat16* __restrict__ yh, __nv_bfloat16* __restrict__ yl,
                          __nv_bfloat16* __restrict__ wh, __nv_bfloat16* __restrict__ wl)
{
    const int i = blockIdx.x * blockDim.x + threadIdx.x;
    if (i >= TOT4) return;
    const float* src; __nv_bfloat16 *hi, *lo; int j;
    if (i < X4)                    { src = x;  hi = xh; lo = xl; j = i; }
    else if (i < X4 + Y4)          { src = y;  hi = yh; lo = yl; j = i - X4; }
    else if (i < X4 + Y4 + W4)     { src = Wq; hi = wh;                lo = wl;                j = i - X4 - Y4; }
    else if (i < X4 + Y4 + 2 * W4) { src = Wk; hi = wh + CDIM * CDIM;  lo = wl + CDIM * CDIM;  j = i - X4 - Y4 - W4; }
    else if (i < X4 + Y4 + 3 * W4) { src = Wv; hi = wh + 2 * CDIM * CDIM; lo = wl + 2 * CDIM * CDIM; j = i - X4 - Y4 - 2 * W4; }
    else                           { src = Wp; hi = wh + 3 * CDIM * CDIM; lo = wl + 3 * CDIM * CDIM; j = i - X4 - Y4 - 3 * W4; }

    float4 v = ((const float4*)src)[j];
    __nv_bfloat162 hh0 = __floats2bfloat162_rn(v.x, v.y);
    __nv_bfloat162 hh1 = __floats2bfloat162_rn(v.z, v.w);
    __nv_bfloat162 ll0 = __floats2bfloat162_rn(v.x - __bfloat162float(hh0.x),
                                               v.y - __bfloat162float(hh0.y));
    __nv_bfloat162 ll1 = __floats2bfloat162_rn(v.z - __bfloat162float(hh1.x),
                                               v.w - __bfloat162float(hh1.y));
    ((__nv_bfloat162*)hi)[j * 2 + 0] = hh0;
    ((__nv_bfloat162*)hi)[j * 2 + 1] = hh1;
    ((__nv_bfloat162*)lo)[j * 2 + 0] = ll0;
    ((__nv_bfloat162*)lo)[j * 2 + 1] = ll1;
}

// ---------------------------------------------------------------------------
// GEMM body (bf16x3 split): C[m][n] = sum_{k in chunks [c0,c1)} A[m][k]*B[n][k]
// CTA tile 128x128, BK=32, 256 threads (8 warps, 4m x 2n), ldmatrix x4.
// ---------------------------------------------------------------------------
#define ROWB   80
#define TILEB  (128 * ROWB)
#define STAGEB (4 * TILEB)
#define GEMM_SMEM (2 * STAGEB)         // 81920 B

#define LOAD_STAGE(cc, buf) do {                                              \
        const uint32_t bo = (uint32_t)(buf) * STAGEB;                         \
        _Pragma("unroll")                                                     \
        for (int s = 0; s < 4; s++) {                                         \
            const int seg = (s + segr) & 3;                                   \
            cp16(sd0 + bo + seg * 16, gp0 + (cc) * 32 + seg * 8);             \
            cp16(sd1 + bo + seg * 16, gp1 + (cc) * 32 + seg * 8);             \
        }                                                                     \
    } while (0)

template <bool OUTF32>
static __device__ __forceinline__ void gemm_body(
    float* __restrict__ C,
    __nv_bfloat16* __restrict__ Ch, __nv_bfloat16* __restrict__ Cl,
    const __nv_bfloat16* __restrict__ Ah, const __nv_bfloat16* __restrict__ Al,
    const __nv_bfloat16* __restrict__ Bh, const __nv_bfloat16* __restrict__ Bl,
    const float* __restrict__ bias, float oscale, int N, int K,
    int bx, int by, int c0, int c1)
{
    const int tid  = threadIdx.x;
    const int wid  = tid >> 5;
    const int lane = tid & 31;
    const int wm   = wid & 3;
    const int wn   = wid >> 2;
    const int g    = lane >> 2;
    const int t4   = lane & 3;
    const int m0   = by * 128;
    const int n0   = bx * 128;

    const uint32_t sb = smem_u32(dsm);

    const int tsel = tid >> 6;
    const int lrow = tid & 63;
    const int segr = (tid >> 3) & 3;
    const __nv_bfloat16* gsrc =
        (tsel == 0) ? Ah : (tsel == 1) ? Al : (tsel == 2) ? Bh : Bl;
    const int trow0 = (tsel < 2) ? m0 : n0;
    const __nv_bfloat16* gp0 = gsrc + (size_t)(trow0 + lrow) * K;
    const __nv_bfloat16* gp1 = gp0 + (size_t)64 * K;
    const uint32_t sd0 = sb + tsel * TILEB + lrow * ROWB;
    const uint32_t sd1 = sd0 + 64 * ROWB;

    const uint32_t lmrow = (uint32_t)(lane & 15) * ROWB + (uint32_t)(lane >> 4) * 16;
    const uint32_t aoff  = (uint32_t)(wm * 32) * ROWB + lmrow;
    const uint32_t boff  = (uint32_t)(wn * 64) * ROWB + lmrow;

    float acc[2][8][4];
#pragma unroll
    for (int mf = 0; mf < 2; mf++)
#pragma unroll
        for (int nf = 0; nf < 8; nf++)
#pragma unroll
            for (int j = 0; j < 4; j++) acc[mf][nf][j] = 0.0f;

    LOAD_STAGE(c0, 0);
    cp_commit();

    for (int c = c0; c < c1; c++) {
        const int buf = (c - c0) & 1;
        if (c + 1 < c1) {
            LOAD_STAGE(c + 1, buf ^ 1);
            cp_commit();
            cp_wait<1>();
        } else {
            cp_wait<0>();
        }
        __syncthreads();

        const uint32_t stg = sb + buf * STAGEB;
        const uint32_t pAh = stg + aoff;
        const uint32_t pAl = stg + TILEB + aoff;
        const uint32_t pBh = stg + 2 * TILEB + boff;
        const uint32_t pBl = stg + 3 * TILEB + boff;

#pragma unroll
        for (int ks = 0; ks < 2; ks++) {
            const uint32_t kb = (uint32_t)(ks * 32);
            uint32_t ah[2][4], al[2][4];
#pragma unroll
            for (int mf = 0; mf < 2; mf++) {
                ldsm_x4(ah[mf], pAh + mf * (16 * ROWB) + kb);
                ldsm_x4(al[mf], pAl + mf * (16 * ROWB) + kb);
            }
#pragma unroll
            for (int nfp = 0; nfp < 4; nfp++) {
                uint32_t bh4[4], bl4[4];
                ldsm_x4(bh4, pBh + nfp * (16 * ROWB) + kb);
                ldsm_x4(bl4, pBl + nfp * (16 * ROWB) + kb);
#pragma unroll
                for (int mf = 0; mf < 2; mf++) {
                    float* cc0 = acc[mf][2 * nfp];
                    float* cc1 = acc[mf][2 * nfp + 1];
                    mma_bf16(cc0, ah[mf][0], ah[mf][1], ah[mf][2], ah[mf][3], bh4[0], bh4[2]);
                    mma_bf16(cc0, ah[mf][0], ah[mf][1], ah[mf][2], ah[mf][3], bl4[0], bl4[2]);
                    mma_bf16(cc0, al[mf][0], al[mf][1], al[mf][2], al[mf][3], bh4[0], bh4[2]);
                    mma_bf16(cc1, ah[mf][0], ah[mf][1], ah[mf][2], ah[mf][3], bh4[1], bh4[3]);
                    mma_bf16(cc1, ah[mf][0], ah[mf][1], ah[mf][2], ah[mf][3], bl4[1], bl4[3]);
                    mma_bf16(cc1, al[mf][0], al[mf][1], al[mf][2], al[mf][3], bh4[1], bh4[3]);
                }
            }
        }
        __syncthreads();
    }

#pragma unroll
    for (int mf = 0; mf < 2; mf++) {
        const int row = m0 + wm * 32 + mf * 16 + g;
#pragma unroll
        for (int nf = 0; nf < 8; nf++) {
            const int col = n0 + wn * 64 + nf * 8 + 2 * t4;
            if (OUTF32) {
                float b0 = 0.0f, b1 = 0.0f;
                if (bias) { b0 = bias[col]; b1 = bias[col + 1]; }
                float2 v0, v1;
                v0.x = acc[mf][nf][0] + b0; v0.y = acc[mf][nf][1] + b1;
                v1.x = acc[mf][nf][2] + b0; v1.y = acc[mf][nf][3] + b1;
                *(float2*)&C[(size_t)row * N + col]       = v0;
                *(float2*)&C[(size_t)(row + 8) * N + col] = v1;
            } else {
                uint32_t h0, l0, h1, l1;
                pack_hl(acc[mf][nf][0] * oscale, acc[mf][nf][1] * oscale, h0, l0);
                pack_hl(acc[mf][nf][2] * oscale, acc[mf][nf][3] * oscale, h1, l1);
                *(uint32_t*)&Ch[(size_t)row * N + col]       = h0;
                *(uint32_t*)&Cl[(size_t)row * N + col]       = l0;
                *(uint32_t*)&Ch[(size_t)(row + 8) * N + col] = h1;
                *(uint32_t*)&Cl[(size_t)(row + 8) * N + col] = l1;
            }
        }
    }
}

// Fused Q/K/V projection: blockIdx.z selects the GEMM; Q (M=2048) early-exits
// its spare m-tiles.  One launch = 1152 working CTAs.
__global__ __launch_bounds__(256, 2)
void proj_fused(const __nv_bfloat16* __restrict__ xh, const __nv_bfloat16* __restrict__ xl,
                const __nv_bfloat16* __restrict__ yh, const __nv_bfloat16* __restrict__ yl,
                const __nv_bfloat16* __restrict__ wh, const __nv_bfloat16* __restrict__ wl,
                __nv_bfloat16* __restrict__ qh, __nv_bfloat16* __restrict__ ql,
                __nv_bfloat16* __restrict__ kh, __nv_bfloat16* __restrict__ kl,
                __nv_bfloat16* __restrict__ vh, __nv_bfloat16* __restrict__ vl)
{
    const int z = blockIdx.z;
    if (z == 0 && blockIdx.y >= (BB * NN) / 128) return;   // Q: only 16 m-tiles

    const __nv_bfloat16* Ah = (z == 0) ? xh : yh;
    const __nv_bfloat16* Al = (z == 0) ? xl : yl;
    const __nv_bfloat16* Bh = wh + (size_t)z * CDIM * CDIM;
    const __nv_bfloat16* Bl = wl + (size_t)z * CDIM * CDIM;
    __nv_bfloat16* Ch = (z == 0) ? qh : (z == 1) ? kh : vh;
    __nv_bfloat16* Cl = (z == 0) ? ql : (z == 1) ? kl : vl;
    const float oscale = (z == 0) ? 0.125f : 1.0f;

    gemm_body<false>(nullptr, Ch, Cl, Ah, Al, Bh, Bl, nullptr, oscale,
                     CDIM, CDIM, blockIdx.x, blockIdx.y, 0, CDIM >> 5);
}

// Output projection, split-K=2: z selects K-half; partials to g_po[z].
__global__ __launch_bounds__(256, 2)
void gemm_out_sk(float* __restrict__ P0, float* __restrict__ P1,
                 const __nv_bfloat16* __restrict__ Ah, const __nv_bfloat16* __restrict__ Al,
                 const __nv_bfloat16* __restrict__ Bh, const __nv_bfloat16* __restrict__ Bl)
{
    const int z = blockIdx.z;
    float* P = z ? P1 : P0;
    const int half = (CDIM >> 5) / 2;   // 16 chunks per half
    gemm_body<true>(P, nullptr, nullptr, Ah, Al, Bh, Bl, nullptr, 1.0f,
                    CDIM, CDIM, blockIdx.x, blockIdx.y, z * half, (z + 1) * half);
}

// merge: out = p0 + p1 + bias
__global__ void merge_out(float* __restrict__ out,
                          const float* __restrict__ p0, const float* __restrict__ p1,
                          const float* __restrict__ bias)
{
    const int i = blockIdx.x * blockDim.x + threadIdx.x;   // float4 index
    if (i >= (BB * NN * CDIM) / 4) return;
    const int col4 = i & (CDIM / 4 - 1);
    float4 a = ((const float4*)p0)[i];
    float4 b = ((const float4*)p1)[i];
    float4 bb = ((const float4*)bias)[col4];
    float4 o;
    o.x = a.x + b.x + bb.x; o.y = a.y + b.y + bb.y;
    o.z = a.z + b.z + bb.z; o.w = a.w + b.w + bb.w;
    ((float4*)out)[i] = o;
}

// ---------------------------------------------------------------------------
// Flash attention on mma.sync (bf16x3) — unchanged (passing)
// ---------------------------------------------------------------------------
#define AQT   128
#define AKT   64
#define AROWB 144
#define QTILE_B (128 * AROWB)
#define QSM_B   (2 * QTILE_B)
#define KTILE_B (64 * AROWB)
#define ASTAGE_B (4 * KTILE_B)
#define ATTN_SMEM (QSM_B + 2 * ASTAGE_B)   // 110592 B

__global__ __launch_bounds__(256, 2)
void attn_mma(__nv_bfloat16* __restrict__ Oh, __nv_bfloat16* __restrict__ Ol,
              const __nv_bfloat16* __restrict__ Qh, const __nv_bfloat16* __restrict__ Ql,
              const __nv_bfloat16* __restrict__ Kh, const __nv_bfloat16* __restrict__ Kl,
              const __nv_bfloat16* __restrict__ Vh, const __nv_bfloat16* __restrict__ Vl)
{
    const int tid  = threadIdx.x;
    const int wid  = tid >> 5;
    const int lane = tid & 31;
    const int g    = lane >> 2;
    const int t4   = lane & 3;
    const int la   = lane & 15;
    const int l8   = la & 7;
    const int lh   = la >> 3;
    const int qt   = blockIdx.x;
    const int h    = blockIdx.y;
    const int b    = blockIdx.z;
    const uint32_t sb = smem_u32(dsm);

    {
#pragma unroll
        for (int j = 0; j < 8; j++) {
            const int idx = tid + j * 256;
            const int hs  = idx >> 10;
            const int rem = idx & 1023;
            const int row = rem >> 3;
            const int seg = rem & 7;
            const __nv_bfloat16* src = (hs ? Ql : Qh) +
                ((size_t)(b * NN + qt * AQT + row) * CDIM + h * DD + seg * 8);
            cp16(sb + hs * QTILE_B + row * AROWB + seg * 16, src);
        }
        cp_commit();
    }

    const size_t kbase = (size_t)b * LLEN * CDIM + h * DD;

#define ISSUE_KV(cc, buf) do {                                                \
        _Pragma("unroll")                                                     \
        for (int j = 0; j < 8; j++) {                                         \
            const int idx  = tid + j * 256;                                   \
            const int tile = idx >> 9;                                        \
            const int rem  = idx & 511;                                       \
            const int row  = rem >> 3;                                        \
            const int seg  = rem & 7;                                         \
            const __nv_bfloat16* src =                                        \
                ((tile == 0) ? Kh : (tile == 1) ? Kl : (tile == 2) ? Vh : Vl) \
                + kbase + (size_t)((cc) * AKT + row) * CDIM + seg * 8;        \
            cp16(sb + QSM_B + (buf) * ASTAGE_B + tile * KTILE_B               \
                 + row * AROWB + seg * 16, src);                              \
        }                                                                     \
    } while (0)

    const uint32_t lmrow = (uint32_t)la * AROWB + (uint32_t)(lane >> 4) * 16;
    const uint32_t qoff  = (uint32_t)(wid * 16) * AROWB + lmrow;
    const uint32_t koff  = lmrow;
    const uint32_t voff  = (uint32_t)((lh * 8 + l8) * AROWB);

    float m0 = -1e30f, m1 = -1e30f, l0 = 0.0f, l1 = 0.0f;
    float o[8][4];
#pragma unroll
    for (int nf = 0; nf < 8; nf++)
#pragma unroll
        for (int j = 0; j < 4; j++) o[nf][j] = 0.0f;

    ISSUE_KV(0, 0); cp_commit();
    cp_wait<0>(); __syncthreads();

    const int NC = LLEN / AKT;
    for (int c = 0; c < NC; c++) {
        const int buf = c & 1;
        if (c + 1 < NC) { ISSUE_KV(c + 1, buf ^ 1); cp_commit(); }

        const uint32_t stg = sb + QSM_B + buf * ASTAGE_B;
        const uint32_t vbh = stg + 2 * KTILE_B + voff;
        const uint32_t vbl = stg + 3 * KTILE_B + voff;

        float s[8][4];
#pragma unroll
        for (int nf = 0; nf < 8; nf++)
#pragma unroll
            for (int j = 0; j < 4; j++) s[nf][j] = 0.0f;

#pragma unroll
        for (int kf = 0; kf < 4; kf++) {
            const uint32_t kb = (uint32_t)(kf * 32);
            uint32_t qh4[4], ql4[4];
            ldsm_x4(qh4, sb + qoff + kb);
            ldsm_x4(ql4, sb + QTILE_B + qoff + kb);
#pragma unroll
            for (int nfp = 0; nfp < 4; nfp++) {
                uint32_t kh4[4], kl4[4];
                ldsm_x4(kh4, stg + koff + nfp * (16 * AROWB) + kb);
                ldsm_x4(kl4, stg + KTILE_B + koff + nfp * (16 * AROWB) + kb);
                float* s0 = s[2 * nfp];
                float* s1 = s[2 * nfp + 1];
                mma_bf16(s0, qh4[0], qh4[1], qh4[2], qh4[3], kh4[0], kh4[2]);
                mma_bf16(s0, qh4[0], qh4[1], qh4[2], qh4[3], kl4[0], kl4[2]);
                mma_bf16(s0, ql4[0], ql4[1], ql4[2], ql4[3], kh4[0], kh4[2]);
                mma_bf16(s1, qh4[0], qh4[1], qh4[2], qh4[3], kh4[1], kh4[3]);
                mma_bf16(s1, qh4[0], qh4[1], qh4[2], qh4[3], kl4[1], kl4[3]);
                mma_bf16(s1, ql4[0], ql4[1], ql4[2], ql4[3], kh4[1], kh4[3]);
            }
        }

        float cm0 = -1e30f, cm1 = -1e30f;
#pragma unroll
        for (int nf = 0; nf < 8; nf++) {
            cm0 = fmaxf(cm0, fmaxf(s[nf][0], s[nf][1]));
            cm1 = fmaxf(cm1, fmaxf(s[nf][2], s[nf][3]));
        }
        cm0 = fmaxf(cm0, __shfl_xor_sync(0xFFFFFFFFu, cm0, 1));
        cm0 = fmaxf(cm0, __shfl_xor_sync(0xFFFFFFFFu, cm0, 2));
        cm1 = fmaxf(cm1, __shfl_xor_sync(0xFFFFFFFFu, cm1, 1));
        cm1 = fmaxf(cm1, __shfl_xor_sync(0xFFFFFFFFu, cm1, 2));
        const float mn0 = fmaxf(m0, cm0);
        const float mn1 = fmaxf(m1, cm1);
        const float al0 = __expf(m0 - mn0);
        const float al1 = __expf(m1 - mn1);
        float sum0 = 0.0f, sum1 = 0.0f;
#pragma unroll
        for (int nf = 0; nf < 8; nf++) {
            s[nf][0] = __expf(s[nf][0] - mn0); sum0 += s[nf][0];
            s[nf][1] = __expf(s[nf][1] - mn0); sum0 += s[nf][1];
            s[nf][2] = __expf(s[nf][2] - mn1); sum1 += s[nf][2];
            s[nf][3] = __expf(s[nf][3] - mn1); sum1 += s[nf][3];
        }
        sum0 += __shfl_xor_sync(0xFFFFFFFFu, sum0, 1);
        sum0 += __shfl_xor_sync(0xFFFFFFFFu, sum0, 2);
        sum1 += __shfl_xor_sync(0xFFFFFFFFu, sum1, 1);
        sum1 += __shfl_xor_sync(0xFFFFFFFFu, sum1, 2);
        l0 = l0 * al0 + sum0; m0 = mn0;
        l1 = l1 * al1 + sum1; m1 = mn1;
#pragma unroll
        for (int nf = 0; nf < 8; nf++) {
            o[nf][0] *= al0; o[nf][1] *= al0;
            o[nf][2] *= al1; o[nf][3] *= al1;
        }

#pragma unroll
        for (int kf = 0; kf < 4; kf++) {
            uint32_t ph[4], pl[4];
            pack_hl(s[2 * kf][0],     s[2 * kf][1],     ph[0], pl[0]);
            pack_hl(s[2 * kf][2],     s[2 * kf][3],     ph[1], pl[1]);
            pack_hl(s[2 * kf + 1][0], s[2 * kf + 1][1], ph[2], pl[2]);
            pack_hl(s[2 * kf + 1][2], s[2 * kf + 1][3], ph[3], pl[3]);
#pragma unroll
            for (int nf = 0; nf < 8; nf++) {
                uint32_t vh0, vh1, vl0, vl1;
                ldsm_x2_t(vh0, vh1, vbh + kf * (16 * AROWB) + nf * 16);
                ldsm_x2_t(vl0, vl1, vbl + kf * (16 * AROWB) + nf * 16);
                mma_bf16(o[nf], ph[0], ph[1], ph[2], ph[3], vh0, vh1);
                mma_bf16(o[nf], ph[0], ph[1], ph[2], ph[3], vl0, vl1);
                mma_bf16(o[nf], pl[0], pl[1], pl[2], pl[3], vh0, vh1);
            }
        }

        if (c + 1 < NC) cp_wait<0>();
        __syncthreads();
    }

    const float inv0 = 1.0f / l0;
    const float inv1 = 1.0f / l1;
    const int row0 = qt * AQT + wid * 16 + g;
#pragma unroll
    for (int nf = 0; nf < 8; nf++) {
        const int col = h * DD + nf * 8 + 2 * t4;
        const size_t a0 = (size_t)(b * NN + row0) * CDIM + col;
        const size_t a1 = (size_t)(b * NN + row0 + 8) * CDIM + col;
        uint32_t h0, lo0, h1, lo1;
        pack_hl(o[nf][0] * inv0, o[nf][1] * inv0, h0, lo0);
        pack_hl(o[nf][2] * inv1, o[nf][3] * inv1, h1, lo1);
        *(uint32_t*)&Oh[a0] = h0; *(uint32_t*)&Ol[a0] = lo0;
        *(uint32_t*)&Oh[a1] = h1; *(uint32_t*)&Ol[a1] = lo1;
    }
#undef ISSUE_KV
}

// ---------------------------------------------------------------------------
// Launch
// ---------------------------------------------------------------------------
extern "C" void kernel_launch(void* const* d_in, const int* in_sizes, int n_in,
                              void* d_out, int out_size)
{
    const float* x  = (const float*)d_in[0];
    const float* y  = (const float*)d_in[1];
    const float* Wq = (const float*)d_in[2];
    const float* Wk = (const float*)d_in[3];
    const float* Wv = (const float*)d_in[4];
    const float* Wp = (const float*)d_in[5];
    const float* bp = (const float*)d_in[6];
    float* out = (float*)d_out;

    __nv_bfloat16 *xh, *xl, *yh, *yl, *wh, *wl;
    __nv_bfloat16 *qh, *ql, *kh, *kl, *vh, *vl, *aoh, *aol;
    float* po;
    cudaGetSymbolAddress((void**)&xh, g_xh);   cudaGetSymbolAddress((void**)&xl, g_xl);
    cudaGetSymbolAddress((void**)&yh, g_yh);   cudaGetSymbolAddress((void**)&yl, g_yl);
    cudaGetSymbolAddress((void**)&wh, g_wh);   cudaGetSymbolAddress((void**)&wl, g_wl);
    cudaGetSymbolAddress((void**)&qh, g_qh);   cudaGetSymbolAddress((void**)&ql, g_ql);
    cudaGetSymbolAddress((void**)&kh, g_kh);   cudaGetSymbolAddress((void**)&kl, g_kl);
    cudaGetSymbolAddress((void**)&vh, g_vh);   cudaGetSymbolAddress((void**)&vl, g_vl);
    cudaGetSymbolAddress((void**)&aoh, g_aoh); cudaGetSymbolAddress((void**)&aol, g_aol);
    cudaGetSymbolAddress((void**)&po, g_po);

    cudaFuncSetAttribute(proj_fused,  cudaFuncAttributeMaxDynamicSharedMemorySize, GEMM_SMEM);
    cudaFuncSetAttribute(gemm_out_sk, cudaFuncAttributeMaxDynamicSharedMemorySize, GEMM_SMEM);
    cudaFuncSetAttribute(attn_mma,    cudaFuncAttributeMaxDynamicSharedMemorySize, ATTN_SMEM);

    float* p0 = po;
    float* p1 = po + BB * NN * CDIM;

    // 1. Fused splits (one launch)
    split_all<<<(TOT4 + 255) / 256, 256>>>(x, y, Wq, Wk, Wv, Wp,
                                           xh, xl, yh, yl, wh, wl);

    // 2. Fused Q/K/V projections (one launch; z = 0:Q, 1:K, 2:V)
    proj_fused<<<dim3(CDIM / 128, (BB * LLEN) / 128, 3), 256, GEMM_SMEM>>>(
        xh, xl, yh, yl, wh, wl, qh, ql, kh, kl, vh, vl);

    // 3. Flash attention on tensor cores -> bf16 hi/lo
    attn_mma<<<dim3(NN / AQT, HH, BB), 256, ATTN_SMEM>>>(
        aoh, aol, qh, ql, kh, kl, vh, vl);

    // 4. Output projection, split-K=2 (256 CTAs -> 2 CTAs/SM)
    gemm_out_sk<<<dim3(CDIM / 128, (BB * NN) / 128, 2), 256, GEMM_SMEM>>>(
        p0, p1, aoh, aol,
        wh + 3 * (size_t)CDIM * CDIM, wl + 3 * (size_t)CDIM * CDIM);

    // 5. Merge partials + bias
    merge_out<<<((BB * NN * CDIM / 4) + 255) / 256, 256>>>(out, p0, p1, bp);
}

// round 11
// speedup vs baseline: 1.0141x; 1.0141x over previous
#include <cuda_runtime.h>
#include <cuda_bf16.h>
#include <math.h>
#include <stdint.h>

// Problem shape (fixed by the dataset)
#define BB   2
#define NN   1024
#define LLEN 4096
#define CDIM 1024
#define HH   16
#define DD   64

// ---------------- scratch (device globals; no allocs allowed) ---------------
__device__ __nv_bfloat16 g_xh[BB * NN * CDIM],   g_xl[BB * NN * CDIM];
__device__ __nv_bfloat16 g_yh[BB * LLEN * CDIM], g_yl[BB * LLEN * CDIM];
__device__ __nv_bfloat16 g_wh[4 * CDIM * CDIM],  g_wl[4 * CDIM * CDIM];
__device__ __nv_bfloat16 g_qh[BB * NN * CDIM],   g_ql[BB * NN * CDIM];   // pre-scaled by 0.125
__device__ __nv_bfloat16 g_kh[BB * LLEN * CDIM], g_kl[BB * LLEN * CDIM];
__device__ __nv_bfloat16 g_vh[BB * LLEN * CDIM], g_vl[BB * LLEN * CDIM];
__device__ __nv_bfloat16 g_aoh[BB * NN * CDIM],  g_aol[BB * NN * CDIM];
__device__ float g_po[2][BB * NN * CDIM];        // split-K partials (16 MB)

extern __shared__ char dsm[];

// ---------------------------------------------------------------------------
// helpers
// ---------------------------------------------------------------------------
static __device__ __forceinline__ uint32_t smem_u32(const void* p) {
    uint32_t a;
    asm("{ .reg .u64 t; cvta.to.shared.u64 t, %1; cvt.u32.u64 %0, t; }"
        : "=r"(a) : "l"(p));
    return a;
}
static __device__ __forceinline__ void cp16(uint32_t dst, const void* src) {
    asm volatile("cp.async.cg.shared.global [%0], [%1], 16;"
                 :: "r"(dst), "l"(src));
}
static __device__ __forceinline__ void cp_commit() {
    asm volatile("cp.async.commit_group;" ::: "memory");
}
template <int N_>
static __device__ __forceinline__ void cp_wait() {
    asm volatile("cp.async.wait_group %0;" :: "n"(N_) : "memory");
}
static __device__ __forceinline__ void mma_bf16(
    float* c, uint32_t a0, uint32_t a1, uint32_t a2, uint32_t a3,
    uint32_t b0, uint32_t b1)
{
    asm volatile(
        "mma.sync.aligned.m16n8k16.row.col.f32.bf16.bf16.f32 "
        "{%0,%1,%2,%3}, {%4,%5,%6,%7}, {%8,%9}, {%0,%1,%2,%3};"
        : "+f"(c[0]), "+f"(c[1]), "+f"(c[2]), "+f"(c[3])
        : "r"(a0), "r"(a1), "r"(a2), "r"(a3), "r"(b0), "r"(b1));
}
static __device__ __forceinline__ void ldsm_x4(uint32_t* r, uint32_t addr) {
    asm volatile("ldmatrix.sync.aligned.m8n8.x4.shared.b16 {%0,%1,%2,%3}, [%4];"
                 : "=r"(r[0]), "=r"(r[1]), "=r"(r[2]), "=r"(r[3]) : "r"(addr));
}
static __device__ __forceinline__ void ldsm_x2_t(uint32_t& r0, uint32_t& r1, uint32_t addr) {
    asm volatile("ldmatrix.sync.aligned.m8n8.x2.trans.shared.b16 {%0,%1}, [%2];"
                 : "=r"(r0), "=r"(r1) : "r"(addr));
}
static __device__ __forceinline__ void pack_hl(
    float a, float b, uint32_t& hi, uint32_t& lo)
{
    __nv_bfloat162 h = __floats2bfloat162_rn(a, b);
    __nv_bfloat162 l = __floats2bfloat162_rn(a - __bfloat162float(h.x),
                                             b - __bfloat162float(h.y));
    hi = *(uint32_t*)&h;
    lo = *(uint32_t*)&l;
}

// ---------------------------------------------------------------------------
// fused split: all six fp32 tensors -> bf16 hi/lo in ONE launch
// ---------------------------------------------------------------------------
#define X4 ((BB * NN * CDIM) / 4)
#define Y4 ((BB * LLEN * CDIM) / 4)
#define W4 ((CDIM * CDIM) / 4)
#define TOT4 (X4 + Y4 + 4 * W4)

__global__ void split_all(const float* __restrict__ x, const float* __restrict__ y,
                          const float* __restrict__ Wq, const float* __restrict__ Wk,
                          const float* __restrict__ Wv, const float* __restrict__ Wp,
                          __nv_bfloat16* __restrict__ xh, __nv_bfloat16* __restrict__ xl,
                          __nv_bfloat16* __restrict__ yh, __nv_bfloat16* __restrict__ yl,
                          __nv_bfloat16* __restrict__ wh, __nv_bfloat16* __restrict__ wl)
{
    const int i = blockIdx.x * blockDim.x + threadIdx.x;
    if (i >= TOT4) return;
    const float* src; __nv_bfloat16 *hi, *lo; int j;
    if (i < X4)                    { src = x;  hi = xh; lo = xl; j = i; }
    else if (i < X4 + Y4)          { src = y;  hi = yh; lo = yl; j = i - X4; }
    else if (i < X4 + Y4 + W4)     { src = Wq; hi = wh;                lo = wl;                j = i - X4 - Y4; }
    else if (i < X4 + Y4 + 2 * W4) { src = Wk; hi = wh + CDIM * CDIM;  lo = wl + CDIM * CDIM;  j = i - X4 - Y4 - W4; }
    else if (i < X4 + Y4 + 3 * W4) { src = Wv; hi = wh + 2 * CDIM * CDIM; lo = wl + 2 * CDIM * CDIM; j = i - X4 - Y4 - 2 * W4; }
    else                           { src = Wp; hi = wh + 3 * CDIM * CDIM; lo = wl + 3 * CDIM * CDIM; j = i - X4 - Y4 - 3 * W4; }

    float4 v = ((const float4*)src)[j];
    __nv_bfloat162 hh0 = __floats2bfloat162_rn(v.x, v.y);
    __nv_bfloat162 hh1 = __floats2bfloat162_rn(v.z, v.w);
    __nv_bfloat162 ll0 = __floats2bfloat162_rn(v.x - __bfloat162float(hh0.x),
                                               v.y - __bfloat162float(hh0.y));
    __nv_bfloat162 ll1 = __floats2bfloat162_rn(v.z - __bfloat162float(hh1.x),
                                               v.w - __bfloat162float(hh1.y));
    ((__nv_bfloat162*)hi)[j * 2 + 0] = hh0;
    ((__nv_bfloat162*)hi)[j * 2 + 1] = hh1;
    ((__nv_bfloat162*)lo)[j * 2 + 0] = ll0;
    ((__nv_bfloat162*)lo)[j * 2 + 1] = ll1;
}

// ---------------------------------------------------------------------------
// GEMM body (bf16x3 split), COMPACT swizzled smem + 3-stage cp.async pipeline.
// Tile = 128 rows x 32 bf16 stored as 64 x 128B lines (2 rows/line):
//   off(r, q) = (r>>1)*128 + ((((r&1)<<2)+q) ^ ((r>>1)&7))*16   (q = 16B seg 0..3)
// Conflict-free for ldmatrix x4; stage = 4 tiles x 8KB = 32KB; 3 stages = 96KB.
// ---------------------------------------------------------------------------
#define CTILE  8192
#define STAGEB (4 * CTILE)             // 32768
#define NSTG   3
#define GEMM_SMEM (NSTG * STAGEB)      // 98304

#define LOAD_STAGE(cc, buf) do {                                              \
        const uint32_t bo = (uint32_t)(buf) * STAGEB;                         \
        _Pragma("unroll")                                                     \
        for (int s = 0; s < 4; s++) {                                         \
            const int seg = (s + segr) & 3;                                   \
            const uint32_t toq = (uint32_t)(((h4 + seg) ^ x0) * 16);          \
            cp16(d0 + bo + toq,        gp0 + (cc) * 32 + seg * 8);            \
            cp16(d0 + bo + toq + 4096, gp1 + (cc) * 32 + seg * 8);            \
        }                                                                     \
    } while (0)

template <bool OUTF32>
static __device__ __forceinline__ void gemm_body(
    float* __restrict__ C,
    __nv_bfloat16* __restrict__ Ch, __nv_bfloat16* __restrict__ Cl,
    const __nv_bfloat16* __restrict__ Ah, const __nv_bfloat16* __restrict__ Al,
    const __nv_bfloat16* __restrict__ Bh, const __nv_bfloat16* __restrict__ Bl,
    const float* __restrict__ bias, float oscale, int N, int K,
    int bx, int by, int c0, int c1)
{
    const int tid  = threadIdx.x;
    const int wid  = tid >> 5;
    const int lane = tid & 31;
    const int wm   = wid & 3;
    const int wn   = wid >> 2;
    const int g    = lane >> 2;
    const int t4   = lane & 3;
    const int m0   = by * 128;
    const int n0   = bx * 128;

    const uint32_t sb = smem_u32(dsm);

    // ---- cp.async mapping: tile = tid/64 (Ah,Al,Bh,Bl); rows lrow, lrow+64 ----
    const int tsel = tid >> 6;
    const int lrow = tid & 63;
    const int segr = (tid >> 3) & 3;
    const int h4   = (lrow & 1) << 2;
    const int x0   = (lrow >> 1) & 7;
    const __nv_bfloat16* gsrc =
        (tsel == 0) ? Ah : (tsel == 1) ? Al : (tsel == 2) ? Bh : Bl;
    const int trow0 = (tsel < 2) ? m0 : n0;
    const __nv_bfloat16* gp0 = gsrc + (size_t)(trow0 + lrow) * K;
    const __nv_bfloat16* gp1 = gp0 + (size_t)64 * K;
    const uint32_t d0 = sb + (uint32_t)tsel * CTILE + (uint32_t)(lrow >> 1) * 128;

    // ---- ldmatrix per-lane constant:
    //  row-in-16 = lane&15, 16B chunk-hi = lane>>4; ks toggles byte-bit5 via XOR
    const int r15 = lane & 15;
    const uint32_t lm0 = (uint32_t)((r15 >> 1) * 128 +
        (((((r15 & 1) << 2) + (lane >> 4)) ^ (r15 >> 1)) << 4));

    float acc[2][8][4];
#pragma unroll
    for (int mf = 0; mf < 2; mf++)
#pragma unroll
        for (int nf = 0; nf < 8; nf++)
#pragma unroll
            for (int j = 0; j < 4; j++) acc[mf][nf][j] = 0.0f;

    // ---- 3-stage prologue ----
    LOAD_STAGE(c0, 0);
    cp_commit();
    if (c0 + 1 < c1) { LOAD_STAGE(c0 + 1, 1); cp_commit(); }

    for (int c = c0; c < c1; c++) {
        const int buf = (c - c0) % NSTG;
        if (c + 2 < c1) {
            LOAD_STAGE(c + 2, (c - c0 + 2) % NSTG);
            cp_commit();
            cp_wait<2>();
        } else if (c + 1 < c1) {
            cp_wait<1>();
        } else {
            cp_wait<0>();
        }
        __syncthreads();

        const uint32_t stg = sb + (uint32_t)buf * STAGEB;
        const uint32_t pAh = stg + (uint32_t)(wm * 32) * 64 + lm0;
        const uint32_t pAl = pAh + CTILE;
        const uint32_t pBh = stg + 2 * CTILE + (uint32_t)(wn * 64) * 64 + lm0;
        const uint32_t pBl = pBh + CTILE;

#pragma unroll
        for (int ks = 0; ks < 2; ks++) {
            const uint32_t kx = (uint32_t)(ks << 5);
            uint32_t ah[2][4], al[2][4];
#pragma unroll
            for (int mf = 0; mf < 2; mf++) {
                ldsm_x4(ah[mf], (pAh + mf * (16 * 64)) ^ kx);
                ldsm_x4(al[mf], (pAl + mf * (16 * 64)) ^ kx);
            }
#pragma unroll
            for (int nfp = 0; nfp < 4; nfp++) {
                uint32_t bh4[4], bl4[4];
                ldsm_x4(bh4, (pBh + nfp * (16 * 64)) ^ kx);
                ldsm_x4(bl4, (pBl + nfp * (16 * 64)) ^ kx);
#pragma unroll
                for (int mf = 0; mf < 2; mf++) {
                    float* cc0 = acc[mf][2 * nfp];
                    float* cc1 = acc[mf][2 * nfp + 1];
                    mma_bf16(cc0, ah[mf][0], ah[mf][1], ah[mf][2], ah[mf][3], bh4[0], bh4[2]);
                    mma_bf16(cc0, ah[mf][0], ah[mf][1], ah[mf][2], ah[mf][3], bl4[0], bl4[2]);
                    mma_bf16(cc0, al[mf][0], al[mf][1], al[mf][2], al[mf][3], bh4[0], bh4[2]);
                    mma_bf16(cc1, ah[mf][0], ah[mf][1], ah[mf][2], ah[mf][3], bh4[1], bh4[3]);
                    mma_bf16(cc1, ah[mf][0], ah[mf][1], ah[mf][2], ah[mf][3], bl4[1], bl4[3]);
                    mma_bf16(cc1, al[mf][0], al[mf][1], al[mf][2], al[mf][3], bh4[1], bh4[3]);
                }
            }
        }
        __syncthreads();
    }

#pragma unroll
    for (int mf = 0; mf < 2; mf++) {
        const int row = m0 + wm * 32 + mf * 16 + g;
#pragma unroll
        for (int nf = 0; nf < 8; nf++) {
            const int col = n0 + wn * 64 + nf * 8 + 2 * t4;
            if (OUTF32) {
                float b0 = 0.0f, b1 = 0.0f;
                if (bias) { b0 = bias[col]; b1 = bias[col + 1]; }
                float2 v0, v1;
                v0.x = acc[mf][nf][0] + b0; v0.y = acc[mf][nf][1] + b1;
                v1.x = acc[mf][nf][2] + b0; v1.y = acc[mf][nf][3] + b1;
                *(float2*)&C[(size_t)row * N + col]       = v0;
                *(float2*)&C[(size_t)(row + 8) * N + col] = v1;
            } else {
                uint32_t h0, l0, h1, l1;
                pack_hl(acc[mf][nf][0] * oscale, acc[mf][nf][1] * oscale, h0, l0);
                pack_hl(acc[mf][nf][2] * oscale, acc[mf][nf][3] * oscale, h1, l1);
                *(uint32_t*)&Ch[(size_t)row * N + col]       = h0;
                *(uint32_t*)&Cl[(size_t)row * N + col]       = l0;
                *(uint32_t*)&Ch[(size_t)(row + 8) * N + col] = h1;
                *(uint32_t*)&Cl[(size_t)(row + 8) * N + col] = l1;
            }
        }
    }
}

// Fused Q/K/V projection (one launch; z = 0:Q, 1:K, 2:V; Q early-exits spares)
__global__ __launch_bounds__(256, 2)
void proj_fused(const __nv_bfloat16* __restrict__ xh, const __nv_bfloat16* __restrict__ xl,
                const __nv_bfloat16* __restrict__ yh, const __nv_bfloat16* __restrict__ yl,
                const __nv_bfloat16* __restrict__ wh, const __nv_bfloat16* __restrict__ wl,
                __nv_bfloat16* __restrict__ qh, __nv_bfloat16* __restrict__ ql,
                __nv_bfloat16* __restrict__ kh, __nv_bfloat16* __restrict__ kl,
                __nv_bfloat16* __restrict__ vh, __nv_bfloat16* __restrict__ vl)
{
    const int z = blockIdx.z;
    if (z == 0 && blockIdx.y >= (BB * NN) / 128) return;

    const __nv_bfloat16* Ah = (z == 0) ? xh : yh;
    const __nv_bfloat16* Al = (z == 0) ? xl : yl;
    const __nv_bfloat16* Bh = wh + (size_t)z * CDIM * CDIM;
    const __nv_bfloat16* Bl = wl + (size_t)z * CDIM * CDIM;
    __nv_bfloat16* Ch = (z == 0) ? qh : (z == 1) ? kh : vh;
    __nv_bfloat16* Cl = (z == 0) ? ql : (z == 1) ? kl : vl;
    const float oscale = (z == 0) ? 0.125f : 1.0f;

    gemm_body<false>(nullptr, Ch, Cl, Ah, Al, Bh, Bl, nullptr, oscale,
                     CDIM, CDIM, blockIdx.x, blockIdx.y, 0, CDIM >> 5);
}

// Output projection, split-K=2
__global__ __launch_bounds__(256, 2)
void gemm_out_sk(float* __restrict__ P0, float* __restrict__ P1,
                 const __nv_bfloat16* __restrict__ Ah, const __nv_bfloat16* __restrict__ Al,
                 const __nv_bfloat16* __restrict__ Bh, const __nv_bfloat16* __restrict__ Bl)
{
    const int z = blockIdx.z;
    float* P = z ? P1 : P0;
    const int half = (CDIM >> 5) / 2;
    gemm_body<true>(P, nullptr, nullptr, Ah, Al, Bh, Bl, nullptr, 1.0f,
                    CDIM, CDIM, blockIdx.x, blockIdx.y, z * half, (z + 1) * half);
}

// merge: out = p0 + p1 + bias
__global__ void merge_out(float* __restrict__ out,
                          const float* __restrict__ p0, const float* __restrict__ p1,
                          const float* __restrict__ bias)
{
    const int i = blockIdx.x * blockDim.x + threadIdx.x;
    if (i >= (BB * NN * CDIM) / 4) return;
    const int col4 = i & (CDIM / 4 - 1);
    float4 a = ((const float4*)p0)[i];
    float4 b = ((const float4*)p1)[i];
    float4 bb = ((const float4*)bias)[col4];
    float4 o;
    o.x = a.x + b.x + bb.x; o.y = a.y + b.y + bb.y;
    o.z = a.z + b.z + bb.z; o.w = a.w + b.w + bb.w;
    ((float4*)out)[i] = o;
}

// ---------------------------------------------------------------------------
// Flash attention on mma.sync (bf16x3) — unchanged from R9 (passing)
// ---------------------------------------------------------------------------
#define AQT   128
#define AKT   64
#define AROWB 144
#define QTILE_B (128 * AROWB)
#define QSM_B   (2 * QTILE_B)
#define KTILE_B (64 * AROWB)
#define ASTAGE_B (4 * KTILE_B)
#define ATTN_SMEM (QSM_B + 2 * ASTAGE_B)   // 110592 B

__global__ __launch_bounds__(256, 2)
void attn_mma(__nv_bfloat16* __restrict__ Oh, __nv_bfloat16* __restrict__ Ol,
              const __nv_bfloat16* __restrict__ Qh, const __nv_bfloat16* __restrict__ Ql,
              const __nv_bfloat16* __restrict__ Kh, const __nv_bfloat16* __restrict__ Kl,
              const __nv_bfloat16* __restrict__ Vh, const __nv_bfloat16* __restrict__ Vl)
{
    const int tid  = threadIdx.x;
    const int wid  = tid >> 5;
    const int lane = tid & 31;
    const int g    = lane >> 2;
    const int t4   = lane & 3;
    const int la   = lane & 15;
    const int l8   = la & 7;
    const int lh   = la >> 3;
    const int qt   = blockIdx.x;
    const int h    = blockIdx.y;
    const int b    = blockIdx.z;
    const uint32_t sb = smem_u32(dsm);

    {
#pragma unroll
        for (int j = 0; j < 8; j++) {
            const int idx = tid + j * 256;
            const int hs  = idx >> 10;
            const int rem = idx & 1023;
            const int row = rem >> 3;
            const int seg = rem & 7;
            const __nv_bfloat16* src = (hs ? Ql : Qh) +
                ((size_t)(b * NN + qt * AQT + row) * CDIM + h * DD + seg * 8);
            cp16(sb + hs * QTILE_B + row * AROWB + seg * 16, src);
        }
        cp_commit();
    }

    const size_t kbase = (size_t)b * LLEN * CDIM + h * DD;

#define ISSUE_KV(cc, buf) do {                                                \
        _Pragma("unroll")                                                     \
        for (int j = 0; j < 8; j++) {                                         \
            const int idx  = tid + j * 256;                                   \
            const int tile = idx >> 9;                                        \
            const int rem  = idx & 511;                                       \
            const int row  = rem >> 3;                                        \
            const int seg  = rem & 7;                                         \
            const __nv_bfloat16* src =                                        \
                ((tile == 0) ? Kh : (tile == 1) ? Kl : (tile == 2) ? Vh : Vl) \
                + kbase + (size_t)((cc) * AKT + row) * CDIM + seg * 8;        \
            cp16(sb + QSM_B + (buf) * ASTAGE_B + tile * KTILE_B               \
                 + row * AROWB + seg * 16, src);                              \
        }                                                                     \
    } while (0)

    const uint32_t lmrow = (uint32_t)la * AROWB + (uint32_t)(lane >> 4) * 16;
    const uint32_t qoff  = (uint32_t)(wid * 16) * AROWB + lmrow;
    const uint32_t koff  = lmrow;
    const uint32_t voff  = (uint32_t)((lh * 8 + l8) * AROWB);

    float m0 = -1e30f, m1 = -1e30f, l0 = 0.0f, l1 = 0.0f;
    float o[8][4];
#pragma unroll
    for (int nf = 0; nf < 8; nf++)
#pragma unroll
        for (int j = 0; j < 4; j++) o[nf][j] = 0.0f;

    ISSUE_KV(0, 0); cp_commit();
    cp_wait<0>(); __syncthreads();

    const int NC = LLEN / AKT;
    for (int c = 0; c < NC; c++) {
        const int buf = c & 1;
        if (c + 1 < NC) { ISSUE_KV(c + 1, buf ^ 1); cp_commit(); }

        const uint32_t stg = sb + QSM_B + buf * ASTAGE_B;
        const uint32_t vbh = stg + 2 * KTILE_B + voff;
        const uint32_t vbl = stg + 3 * KTILE_B + voff;

        float s[8][4];
#pragma unroll
        for (int nf = 0; nf < 8; nf++)
#pragma unroll
            for (int j = 0; j < 4; j++) s[nf][j] = 0.0f;

#pragma unroll
        for (int kf = 0; kf < 4; kf++) {
            const uint32_t kb = (uint32_t)(kf * 32);
            uint32_t qh4[4], ql4[4];
            ldsm_x4(qh4, sb + qoff + kb);
            ldsm_x4(ql4, sb + QTILE_B + qoff + kb);
#pragma unroll
            for (int nfp = 0; nfp < 4; nfp++) {
                uint32_t kh4[4], kl4[4];
                ldsm_x4(kh4, stg + koff + nfp * (16 * AROWB) + kb);
                ldsm_x4(kl4, stg + KTILE_B + koff + nfp * (16 * AROWB) + kb);
                float* s0 = s[2 * nfp];
                float* s1 = s[2 * nfp + 1];
                mma_bf16(s0, qh4[0], qh4[1], qh4[2], qh4[3], kh4[0], kh4[2]);
                mma_bf16(s0, qh4[0], qh4[1], qh4[2], qh4[3], kl4[0], kl4[2]);
                mma_bf16(s0, ql4[0], ql4[1], ql4[2], ql4[3], kh4[0], kh4[2]);
                mma_bf16(s1, qh4[0], qh4[1], qh4[2], qh4[3], kh4[1], kh4[3]);
                mma_bf16(s1, qh4[0], qh4[1], qh4[2], qh4[3], kl4[1], kl4[3]);
                mma_bf16(s1, ql4[0], ql4[1], ql4[2], ql4[3], kh4[1], kh4[3]);
            }
        }

        float cm0 = -1e30f, cm1 = -1e30f;
#pragma unroll
        for (int nf = 0; nf < 8; nf++) {
            cm0 = fmaxf(cm0, fmaxf(s[nf][0], s[nf][1]));
            cm1 = fmaxf(cm1, fmaxf(s[nf][2], s[nf][3]));
        }
        cm0 = fmaxf(cm0, __shfl_xor_sync(0xFFFFFFFFu, cm0, 1));
        cm0 = fmaxf(cm0, __shfl_xor_sync(0xFFFFFFFFu, cm0, 2));
        cm1 = fmaxf(cm1, __shfl_xor_sync(0xFFFFFFFFu, cm1, 1));
        cm1 = fmaxf(cm1, __shfl_xor_sync(0xFFFFFFFFu, cm1, 2));
        const float mn0 = fmaxf(m0, cm0);
        const float mn1 = fmaxf(m1, cm1);
        const float al0 = __expf(m0 - mn0);
        const float al1 = __expf(m1 - mn1);
        float sum0 = 0.0f, sum1 = 0.0f;
#pragma unroll
        for (int nf = 0; nf < 8; nf++) {
            s[nf][0] = __expf(s[nf][0] - mn0); sum0 += s[nf][0];
            s[nf][1] = __expf(s[nf][1] - mn0); sum0 += s[nf][1];
            s[nf][2] = __expf(s[nf][2] - mn1); sum1 += s[nf][2];
            s[nf][3] = __expf(s[nf][3] - mn1); sum1 += s[nf][3];
        }
        sum0 += __shfl_xor_sync(0xFFFFFFFFu, sum0, 1);
        sum0 += __shfl_xor_sync(0xFFFFFFFFu, sum0, 2);
        sum1 += __shfl_xor_sync(0xFFFFFFFFu, sum1, 1);
        sum1 += __shfl_xor_sync(0xFFFFFFFFu, sum1, 2);
        l0 = l0 * al0 + sum0; m0 = mn0;
        l1 = l1 * al1 + sum1; m1 = mn1;
#pragma unroll
        for (int nf = 0; nf < 8; nf++) {
            o[nf][0] *= al0; o[nf][1] *= al0;
            o[nf][2] *= al1; o[nf][3] *= al1;
        }

#pragma unroll
        for (int kf = 0; kf < 4; kf++) {
            uint32_t ph[4], pl[4];
            pack_hl(s[2 * kf][0],     s[2 * kf][1],     ph[0], pl[0]);
            pack_hl(s[2 * kf][2],     s[2 * kf][3],     ph[1], pl[1]);
            pack_hl(s[2 * kf + 1][0], s[2 * kf + 1][1], ph[2], pl[2]);
            pack_hl(s[2 * kf + 1][2], s[2 * kf + 1][3], ph[3], pl[3]);
#pragma unroll
            for (int nf = 0; nf < 8; nf++) {
                uint32_t vh0, vh1, vl0, vl1;
                ldsm_x2_t(vh0, vh1, vbh + kf * (16 * AROWB) + nf * 16);
                ldsm_x2_t(vl0, vl1, vbl + kf * (16 * AROWB) + nf * 16);
                mma_bf16(o[nf], ph[0], ph[1], ph[2], ph[3], vh0, vh1);
                mma_bf16(o[nf], ph[0], ph[1], ph[2], ph[3], vl0, vl1);
                mma_bf16(o[nf], pl[0], pl[1], pl[2], pl[3], vh0, vh1);
            }
        }

        if (c + 1 < NC) cp_wait<0>();
        __syncthreads();
    }

    const float inv0 = 1.0f / l0;
    const float inv1 = 1.0f / l1;
    const int row0 = qt * AQT + wid * 16 + g;
#pragma unroll
    for (int nf = 0; nf < 8; nf++) {
        const int col = h * DD + nf * 8 + 2 * t4;
        const size_t a0 = (size_t)(b * NN + row0) * CDIM + col;
        const size_t a1 = (size_t)(b * NN + row0 + 8) * CDIM + col;
        uint32_t h0, lo0, h1, lo1;
        pack_hl(o[nf][0] * inv0, o[nf][1] * inv0, h0, lo0);
        pack_hl(o[nf][2] * inv1, o[nf][3] * inv1, h1, lo1);
        *(uint32_t*)&Oh[a0] = h0; *(uint32_t*)&Ol[a0] = lo0;
        *(uint32_t*)&Oh[a1] = h1; *(uint32_t*)&Ol[a1] = lo1;
    }
#undef ISSUE_KV
}

// ---------------------------------------------------------------------------
// Launch
// ---------------------------------------------------------------------------
extern "C" void kernel_launch(void* const* d_in, const int* in_sizes, int n_in,
                              void* d_out, int out_size)
{
    const float* x  = (const float*)d_in[0];
    const float* y  = (const float*)d_in[1];
    const float* Wq = (const float*)d_in[2];
    const float* Wk = (const float*)d_in[3];
    const float* Wv = (const float*)d_in[4];
    const float* Wp = (const float*)d_in[5];
    const float* bp = (const float*)d_in[6];
    float* out = (float*)d_out;

    __nv_bfloat16 *xh, *xl, *yh, *yl, *wh, *wl;
    __nv_bfloat16 *qh, *ql, *kh, *kl, *vh, *vl, *aoh, *aol;
    float* po;
    cudaGetSymbolAddress((void**)&xh, g_xh);   cudaGetSymbolAddress((void**)&xl, g_xl);
    cudaGetSymbolAddress((void**)&yh, g_yh);   cudaGetSymbolAddress((void**)&yl, g_yl);
    cudaGetSymbolAddress((void**)&wh, g_wh);   cudaGetSymbolAddress((void**)&wl, g_wl);
    cudaGetSymbolAddress((void**)&qh, g_qh);   cudaGetSymbolAddress((void**)&ql, g_ql);
    cudaGetSymbolAddress((void**)&kh, g_kh);   cudaGetSymbolAddress((void**)&kl, g_kl);
    cudaGetSymbolAddress((void**)&vh, g_vh);   cudaGetSymbolAddress((void**)&vl, g_vl);
    cudaGetSymbolAddress((void**)&aoh, g_aoh); cudaGetSymbolAddress((void**)&aol, g_aol);
    cudaGetSymbolAddress((void**)&po, g_po);

    cudaFuncSetAttribute(proj_fused,  cudaFuncAttributeMaxDynamicSharedMemorySize, GEMM_SMEM);
    cudaFuncSetAttribute(gemm_out_sk, cudaFuncAttributeMaxDynamicSharedMemorySize, GEMM_SMEM);
    cudaFuncSetAttribute(attn_mma,    cudaFuncAttributeMaxDynamicSharedMemorySize, ATTN_SMEM);

    float* p0 = po;
    float* p1 = po + BB * NN * CDIM;

    // 1. Fused splits (one launch)
    split_all<<<(TOT4 + 255) / 256, 256>>>(x, y, Wq, Wk, Wv, Wp,
                                           xh, xl, yh, yl, wh, wl);

    // 2. Fused Q/K/V projections (one launch; z = 0:Q, 1:K, 2:V)
    proj_fused<<<dim3(CDIM / 128, (BB * LLEN) / 128, 3), 256, GEMM_SMEM>>>(
        xh, xl, yh, yl, wh, wl, qh, ql, kh, kl, vh, vl);

    // 3. Flash attention on tensor cores -> bf16 hi/lo
    attn_mma<<<dim3(NN / AQT, HH, BB), 256, ATTN_SMEM>>>(
        aoh, aol, qh, ql, kh, kl, vh, vl);

    // 4. Output projection, split-K=2
    gemm_out_sk<<<dim3(CDIM / 128, (BB * NN) / 128, 2), 256, GEMM_SMEM>>>(
        p0, p1, aoh, aol,
        wh + 3 * (size_t)CDIM * CDIM, wl + 3 * (size_t)CDIM * CDIM);

    // 5. Merge partials + bias
    merge_out<<<((BB * NN * CDIM / 4) + 255) / 256, 256>>>(out, p0, p1, bp);
}

// round 12
// speedup vs baseline: 2.0066x; 1.9788x over previous
#include <cuda_runtime.h>
#include <cuda_fp16.h>
#include <math.h>
#include <stdint.h>

// Problem shape (fixed by the dataset)
#define BB   2
#define NN   1024
#define LLEN 4096
#define CDIM 1024
#define HH   16
#define DD   64

// ---------------- scratch (device globals; no allocs allowed) ---------------
__device__ __half g_xh[BB * NN * CDIM],   g_xl[BB * NN * CDIM];
__device__ __half g_yh[BB * LLEN * CDIM], g_yl[BB * LLEN * CDIM];
__device__ __half g_w[4 * CDIM * CDIM];                    // single fp16 weights
__device__ __half g_qh[BB * NN * CDIM],   g_ql[BB * NN * CDIM];   // pre-scaled 0.125
__device__ __half g_k1[BB * LLEN * CDIM];                  // single fp16
__device__ __half g_v1[BB * LLEN * CDIM];                  // single fp16
__device__ __half g_aoh[BB * NN * CDIM],  g_aol[BB * NN * CDIM];
__device__ float  g_po[2][BB * NN * CDIM];                 // split-K partials

extern __shared__ char dsm[];

// ---------------------------------------------------------------------------
// helpers
// ---------------------------------------------------------------------------
static __device__ __forceinline__ uint32_t smem_u32(const void* p) {
    uint32_t a;
    asm("{ .reg .u64 t; cvta.to.shared.u64 t, %1; cvt.u32.u64 %0, t; }"
        : "=r"(a) : "l"(p));
    return a;
}
static __device__ __forceinline__ void cp16(uint32_t dst, const void* src) {
    asm volatile("cp.async.cg.shared.global [%0], [%1], 16;"
                 :: "r"(dst), "l"(src));
}
static __device__ __forceinline__ void cp_commit() {
    asm volatile("cp.async.commit_group;" ::: "memory");
}
template <int N_>
static __device__ __forceinline__ void cp_wait() {
    asm volatile("cp.async.wait_group %0;" :: "n"(N_) : "memory");
}
static __device__ __forceinline__ void mma_f16(
    float* c, uint32_t a0, uint32_t a1, uint32_t a2, uint32_t a3,
    uint32_t b0, uint32_t b1)
{
    asm volatile(
        "mma.sync.aligned.m16n8k16.row.col.f32.f16.f16.f32 "
        "{%0,%1,%2,%3}, {%4,%5,%6,%7}, {%8,%9}, {%0,%1,%2,%3};"
        : "+f"(c[0]), "+f"(c[1]), "+f"(c[2]), "+f"(c[3])
        : "r"(a0), "r"(a1), "r"(a2), "r"(a3), "r"(b0), "r"(b1));
}
static __device__ __forceinline__ void ldsm_x4(uint32_t* r, uint32_t addr) {
    asm volatile("ldmatrix.sync.aligned.m8n8.x4.shared.b16 {%0,%1,%2,%3}, [%4];"
                 : "=r"(r[0]), "=r"(r[1]), "=r"(r[2]), "=r"(r[3]) : "r"(addr));
}
static __device__ __forceinline__ void ldsm_x2_t(uint32_t& r0, uint32_t& r1, uint32_t addr) {
    asm volatile("ldmatrix.sync.aligned.m8n8.x2.trans.shared.b16 {%0,%1}, [%2];"
                 : "=r"(r0), "=r"(r1) : "r"(addr));
}
// fp16 hi + residual lo
static __device__ __forceinline__ void pack_hl16(
    float a, float b, uint32_t& hi, uint32_t& lo)
{
    __half2 h = __floats2half2_rn(a, b);
    __half2 l = __floats2half2_rn(a - __half2float(__low2half(h)),
                                  b - __half2float(__high2half(h)));
    hi = *(uint32_t*)&h;
    lo = *(uint32_t*)&l;
}

// ---------------------------------------------------------------------------
// fused convert: x, y -> fp16 hi/lo;  Wq..Wp -> single fp16.  ONE launch.
// ---------------------------------------------------------------------------
#define X4 ((BB * NN * CDIM) / 4)
#define Y4 ((BB * LLEN * CDIM) / 4)
#define W4 ((CDIM * CDIM) / 4)
#define TOT4 (X4 + Y4 + 4 * W4)

__global__ void convert_all(const float* __restrict__ x, const float* __restrict__ y,
                            const float* __restrict__ Wq, const float* __restrict__ Wk,
                            const float* __restrict__ Wv, const float* __restrict__ Wp,
                            __half* __restrict__ xh, __half* __restrict__ xl,
                            __half* __restrict__ yh, __half* __restrict__ yl,
                            __half* __restrict__ w)
{
    const int i = blockIdx.x * blockDim.x + threadIdx.x;
    if (i >= TOT4) return;

    if (i < X4 + Y4) {   // hi/lo split for activations
        const float* src; __half *hi, *lo; int j;
        if (i < X4) { src = x; hi = xh; lo = xl; j = i; }
        else        { src = y; hi = yh; lo = yl; j = i - X4; }
        float4 v = ((const float4*)src)[j];
        uint32_t h0, l0, h1, l1;
        pack_hl16(v.x, v.y, h0, l0);
        pack_hl16(v.z, v.w, h1, l1);
        ((uint32_t*)hi)[j * 2 + 0] = h0;
        ((uint32_t*)hi)[j * 2 + 1] = h1;
        ((uint32_t*)lo)[j * 2 + 0] = l0;
        ((uint32_t*)lo)[j * 2 + 1] = l1;
    } else {             // single fp16 for weights
        int r = i - X4 - Y4;
        const int wsel = r / W4;
        const int j = r - wsel * W4;
        const float* src = (wsel == 0) ? Wq : (wsel == 1) ? Wk : (wsel == 2) ? Wv : Wp;
        float4 v = ((const float4*)src)[j];
        __half2 a = __floats2half2_rn(v.x, v.y);
        __half2 b = __floats2half2_rn(v.z, v.w);
        ((uint32_t*)w)[(size_t)wsel * (W4 * 2) + j * 2 + 0] = *(uint32_t*)&a;
        ((uint32_t*)w)[(size_t)wsel * (W4 * 2) + j * 2 + 1] = *(uint32_t*)&b;
    }
}

// ---------------------------------------------------------------------------
// GEMM body (fp16 2-term: C = (Ah+Al) * B^T), BK=64, tile 128x128, 256 thr.
// Smem row = 128B (64 fp16), swizzle: off(r, s) = r*128 + ((s ^ (r&7))<<4).
// 3 operand tiles (Ah, Al, B) x 16KB; 2 stages = 96KB -> 2 CTAs/SM.
// omode: 0 = fp32 C, 1 = fp16 hi/lo (Ch, Cl, *oscale), 2 = fp16 single (Cs).
// ---------------------------------------------------------------------------
#define GTILE  16384
#define STAGEB (3 * GTILE)             // 49152
#define GEMM_SMEM (2 * STAGEB)         // 98304

#define LOAD_STAGE(cc, buf) do {                                              \
        const uint32_t bo = (uint32_t)(buf) * STAGEB;                         \
        _Pragma("unroll")                                                     \
        for (int k = 0; k < 4; k++) {                                         \
            const int j   = tid + k * 256;                                    \
            const int row = j >> 3;                                           \
            const int s   = j & 7;                                            \
            const uint32_t doff = (uint32_t)(row * 128 + (((s) ^ (row & 7)) << 4)); \
            cp16(sb + bo + doff,             Ah + (size_t)(m0 + row) * K + (cc) * 64 + s * 8); \
            cp16(sb + bo + GTILE + doff,     Al + (size_t)(m0 + row) * K + (cc) * 64 + s * 8); \
            cp16(sb + bo + 2 * GTILE + doff, Bs + (size_t)(n0 + row) * K + (cc) * 64 + s * 8); \
        }                                                                     \
    } while (0)

static __device__ __forceinline__ void gemm_body(
    float* __restrict__ C,
    __half* __restrict__ Ch, __half* __restrict__ Cl, __half* __restrict__ Cs,
    const __half* __restrict__ Ah, const __half* __restrict__ Al,
    const __half* __restrict__ Bs,
    float oscale, int omode, int N, int K, int bx, int by, int c0, int c1)
{
    const int tid  = threadIdx.x;
    const int wid  = tid >> 5;
    const int lane = tid & 31;
    const int wm   = wid & 3;
    const int wn   = wid >> 2;
    const int g    = lane >> 2;
    const int t4   = lane & 3;
    const int m0   = by * 128;
    const int n0   = bx * 128;
    const int r15  = lane & 15;
    const int hi8  = lane >> 4;
    const int r7   = r15 & 7;

    const uint32_t sb = smem_u32(dsm);

    float acc[2][8][4];
#pragma unroll
    for (int mf = 0; mf < 2; mf++)
#pragma unroll
        for (int nf = 0; nf < 8; nf++)
#pragma unroll
            for (int j = 0; j < 4; j++) acc[mf][nf][j] = 0.0f;

    LOAD_STAGE(c0, 0);
    cp_commit();

    for (int c = c0; c < c1; c++) {
        const int buf = (c - c0) & 1;
        if (c + 1 < c1) {
            LOAD_STAGE(c + 1, buf ^ 1);
            cp_commit();
            cp_wait<1>();
        } else {
            cp_wait<0>();
        }
        __syncthreads();

        const uint32_t stg = sb + (uint32_t)buf * STAGEB;

#pragma unroll
        for (int ks = 0; ks < 4; ks++) {
            const uint32_t sx = (uint32_t)((((2 * ks + hi8) ^ r7)) << 4);
            uint32_t ah[2][4], al[2][4];
#pragma unroll
            for (int mf = 0; mf < 2; mf++) {
                const uint32_t ra = (uint32_t)((wm * 32 + mf * 16 + r15) * 128) + sx;
                ldsm_x4(ah[mf], stg + ra);
                ldsm_x4(al[mf], stg + GTILE + ra);
            }
#pragma unroll
            for (int nfp = 0; nfp < 4; nfp++) {
                uint32_t b4[4];
                ldsm_x4(b4, stg + 2 * GTILE +
                        (uint32_t)((wn * 64 + nfp * 16 + r15) * 128) + sx);
#pragma unroll
                for (int mf = 0; mf < 2; mf++) {
                    float* cc0 = acc[mf][2 * nfp];
                    float* cc1 = acc[mf][2 * nfp + 1];
                    mma_f16(cc0, ah[mf][0], ah[mf][1], ah[mf][2], ah[mf][3], b4[0], b4[2]);
                    mma_f16(cc0, al[mf][0], al[mf][1], al[mf][2], al[mf][3], b4[0], b4[2]);
                    mma_f16(cc1, ah[mf][0], ah[mf][1], ah[mf][2], ah[mf][3], b4[1], b4[3]);
                    mma_f16(cc1, al[mf][0], al[mf][1], al[mf][2], al[mf][3], b4[1], b4[3]);
                }
            }
        }
        __syncthreads();
    }

#pragma unroll
    for (int mf = 0; mf < 2; mf++) {
        const int row = m0 + wm * 32 + mf * 16 + g;
#pragma unroll
        for (int nf = 0; nf < 8; nf++) {
            const int col = n0 + wn * 64 + nf * 8 + 2 * t4;
            if (omode == 0) {
                float2 v0, v1;
                v0.x = acc[mf][nf][0]; v0.y = acc[mf][nf][1];
                v1.x = acc[mf][nf][2]; v1.y = acc[mf][nf][3];
                *(float2*)&C[(size_t)row * N + col]       = v0;
                *(float2*)&C[(size_t)(row + 8) * N + col] = v1;
            } else if (omode == 1) {
                uint32_t h0, l0, h1, l1;
                pack_hl16(acc[mf][nf][0] * oscale, acc[mf][nf][1] * oscale, h0, l0);
                pack_hl16(acc[mf][nf][2] * oscale, acc[mf][nf][3] * oscale, h1, l1);
                *(uint32_t*)&Ch[(size_t)row * N + col]       = h0;
                *(uint32_t*)&Cl[(size_t)row * N + col]       = l0;
                *(uint32_t*)&Ch[(size_t)(row + 8) * N + col] = h1;
                *(uint32_t*)&Cl[(size_t)(row + 8) * N + col] = l1;
            } else {
                __half2 v0 = __floats2half2_rn(acc[mf][nf][0], acc[mf][nf][1]);
                __half2 v1 = __floats2half2_rn(acc[mf][nf][2], acc[mf][nf][3]);
                *(uint32_t*)&Cs[(size_t)row * N + col]       = *(uint32_t*)&v0;
                *(uint32_t*)&Cs[(size_t)(row + 8) * N + col] = *(uint32_t*)&v1;
            }
        }
    }
}

// Fused Q/K/V projection (z = 0:Q split-out, 1:K single, 2:V single)
__global__ __launch_bounds__(256, 2)
void proj_fused(const __half* __restrict__ xh, const __half* __restrict__ xl,
                const __half* __restrict__ yh, const __half* __restrict__ yl,
                const __half* __restrict__ w,
                __half* __restrict__ qh, __half* __restrict__ ql,
                __half* __restrict__ k1, __half* __restrict__ v1)
{
    const int z = blockIdx.z;
    if (z == 0 && blockIdx.y >= (BB * NN) / 128) return;

    const __half* Ah = (z == 0) ? xh : yh;
    const __half* Al = (z == 0) ? xl : yl;
    const __half* Bs = w + (size_t)z * CDIM * CDIM;
    if (z == 0)
        gemm_body(nullptr, qh, ql, nullptr, Ah, Al, Bs, 0.125f, 1,
                  CDIM, CDIM, blockIdx.x, blockIdx.y, 0, CDIM >> 6);
    else
        gemm_body(nullptr, nullptr, nullptr, (z == 1) ? k1 : v1, Ah, Al, Bs, 1.0f, 2,
                  CDIM, CDIM, blockIdx.x, blockIdx.y, 0, CDIM >> 6);
}

// Output projection, split-K=2
__global__ __launch_bounds__(256, 2)
void gemm_out_sk(float* __restrict__ P0, float* __restrict__ P1,
                 const __half* __restrict__ Ah, const __half* __restrict__ Al,
                 const __half* __restrict__ Bs)
{
    const int z = blockIdx.z;
    const int half = (CDIM >> 6) / 2;   // 8 chunks per half
    gemm_body(z ? P1 : P0, nullptr, nullptr, nullptr, Ah, Al, Bs, 1.0f, 0,
              CDIM, CDIM, blockIdx.x, blockIdx.y, z * half, (z + 1) * half);
}

// merge: out = p0 + p1 + bias
__global__ void merge_out(float* __restrict__ out,
                          const float* __restrict__ p0, const float* __restrict__ p1,
                          const float* __restrict__ bias)
{
    const int i = blockIdx.x * blockDim.x + threadIdx.x;
    if (i >= (BB * NN * CDIM) / 4) return;
    const int col4 = i & (CDIM / 4 - 1);
    float4 a = ((const float4*)p0)[i];
    float4 b = ((const float4*)p1)[i];
    float4 bb = ((const float4*)bias)[col4];
    float4 o;
    o.x = a.x + b.x + bb.x; o.y = a.y + b.y + bb.y;
    o.z = a.z + b.z + bb.z; o.w = a.w + b.w + bb.w;
    ((float4*)out)[i] = o;
}

// ---------------------------------------------------------------------------
// Flash attention, fp16 2-term.  CTA = 128 queries of one (b,h); 8 warps x 16
// rows, warp-local softmax.  Q (hi/lo) persistent in smem; K, V single fp16,
// double-buffered.  S = (Qh+Ql)K^T ; O += (Ph+Pl)V.
// ---------------------------------------------------------------------------
#define QSM_B   32768                   // Qh + Ql tiles (16KB each)
#define KVTILE  8192                    // 64 rows x 128B
#define ASTAGE_B (2 * KVTILE)           // K + V
#define ATTN_SMEM (QSM_B + 2 * ASTAGE_B)   // 65536

__global__ __launch_bounds__(256, 2)
void attn_mma(__half* __restrict__ Oh, __half* __restrict__ Ol,
              const __half* __restrict__ Qh, const __half* __restrict__ Ql,
              const __half* __restrict__ K1, const __half* __restrict__ V1)
{
    const int tid  = threadIdx.x;
    const int wid  = tid >> 5;
    const int lane = tid & 31;
    const int g    = lane >> 2;
    const int t4   = lane & 3;
    const int r15  = lane & 15;
    const int hi8  = lane >> 4;
    const int r7   = r15 & 7;
    const int l8   = lane & 7;
    const int lh   = (lane >> 3) & 1;
    const int qt   = blockIdx.x;
    const int h    = blockIdx.y;
    const int b    = blockIdx.z;
    const uint32_t sb = smem_u32(dsm);

    // ---- stage Q (hi/lo) into persistent smem ----
    {
#pragma unroll
        for (int k = 0; k < 8; k++) {
            const int j   = tid + k * 256;
            const int hs  = j >> 10;
            const int rem = j & 1023;
            const int row = rem >> 3;
            const int s   = rem & 7;
            const __half* src = (hs ? Ql : Qh) +
                ((size_t)(b * NN + qt * 128 + row) * CDIM + h * DD + s * 8);
            cp16(sb + hs * 16384 + row * 128 + ((s ^ (row & 7)) << 4), src);
        }
        cp_commit();
    }

    const size_t kbase = (size_t)b * LLEN * CDIM + h * DD;

#define ISSUE_KV(cc, buf) do {                                                \
        _Pragma("unroll")                                                     \
        for (int k = 0; k < 4; k++) {                                         \
            const int j    = tid + k * 256;                                   \
            const int tile = j >> 9;                                          \
            const int rem  = j & 511;                                         \
            const int row  = rem >> 3;                                        \
            const int s    = rem & 7;                                         \
            const __half* src = (tile ? V1 : K1) + kbase +                    \
                (size_t)((cc) * 64 + row) * CDIM + s * 8;                     \
            cp16(sb + QSM_B + (buf) * ASTAGE_B + tile * KVTILE                \
                 + row * 128 + ((s ^ (row & 7)) << 4), src);                  \
        }                                                                     \
    } while (0)

    float m0 = -1e30f, m1 = -1e30f, l0 = 0.0f, l1 = 0.0f;
    float o[8][4];
#pragma unroll
    for (int nf = 0; nf < 8; nf++)
#pragma unroll
        for (int j = 0; j < 4; j++) o[nf][j] = 0.0f;

    ISSUE_KV(0, 0); cp_commit();
    cp_wait<0>(); __syncthreads();

    const uint32_t qrow = (uint32_t)((wid * 16 + r15) * 128);

    const int NC = LLEN / 64;
    for (int c = 0; c < NC; c++) {
        const int buf = c & 1;
        if (c + 1 < NC) { ISSUE_KV(c + 1, buf ^ 1); cp_commit(); }

        const uint32_t stg = sb + QSM_B + buf * ASTAGE_B;

        // ---- S = (Qh+Ql) K^T ----
        float s[8][4];
#pragma unroll
        for (int nf = 0; nf < 8; nf++)
#pragma unroll
            for (int j = 0; j < 4; j++) s[nf][j] = 0.0f;

#pragma unroll
        for (int kf = 0; kf < 4; kf++) {
            const uint32_t sx = (uint32_t)((((2 * kf + hi8) ^ r7)) << 4);
            uint32_t qh4[4], ql4[4];
            ldsm_x4(qh4, sb + qrow + sx);
            ldsm_x4(ql4, sb + 16384 + qrow + sx);
#pragma unroll
            for (int nfp = 0; nfp < 4; nfp++) {
                uint32_t k4[4];
                ldsm_x4(k4, stg + (uint32_t)((nfp * 16 + r15) * 128) + sx);
                float* s0 = s[2 * nfp];
                float* s1 = s[2 * nfp + 1];
                mma_f16(s0, qh4[0], qh4[1], qh4[2], qh4[3], k4[0], k4[2]);
                mma_f16(s0, ql4[0], ql4[1], ql4[2], ql4[3], k4[0], k4[2]);
                mma_f16(s1, qh4[0], qh4[1], qh4[2], qh4[3], k4[1], k4[3]);
                mma_f16(s1, ql4[0], ql4[1], ql4[2], ql4[3], k4[1], k4[3]);
            }
        }

        // ---- online softmax (warp-local; rows g and g+8) ----
        float cm0 = -1e30f, cm1 = -1e30f;
#pragma unroll
        for (int nf = 0; nf < 8; nf++) {
            cm0 = fmaxf(cm0, fmaxf(s[nf][0], s[nf][1]));
            cm1 = fmaxf(cm1, fmaxf(s[nf][2], s[nf][3]));
        }
        cm0 = fmaxf(cm0, __shfl_xor_sync(0xFFFFFFFFu, cm0, 1));
        cm0 = fmaxf(cm0, __shfl_xor_sync(0xFFFFFFFFu, cm0, 2));
        cm1 = fmaxf(cm1, __shfl_xor_sync(0xFFFFFFFFu, cm1, 1));
        cm1 = fmaxf(cm1, __shfl_xor_sync(0xFFFFFFFFu, cm1, 2));
        const float mn0 = fmaxf(m0, cm0);
        const float mn1 = fmaxf(m1, cm1);
        const float al0 = __expf(m0 - mn0);
        const float al1 = __expf(m1 - mn1);
        float sum0 = 0.0f, sum1 = 0.0f;
#pragma unroll
        for (int nf = 0; nf < 8; nf++) {
            s[nf][0] = __expf(s[nf][0] - mn0); sum0 += s[nf][0];
            s[nf][1] = __expf(s[nf][1] - mn0); sum0 += s[nf][1];
            s[nf][2] = __expf(s[nf][2] - mn1); sum1 += s[nf][2];
            s[nf][3] = __expf(s[nf][3] - mn1); sum1 += s[nf][3];
        }
        sum0 += __shfl_xor_sync(0xFFFFFFFFu, sum0, 1);
        sum0 += __shfl_xor_sync(0xFFFFFFFFu, sum0, 2);
        sum1 += __shfl_xor_sync(0xFFFFFFFFu, sum1, 1);
        sum1 += __shfl_xor_sync(0xFFFFFFFFu, sum1, 2);
        l0 = l0 * al0 + sum0; m0 = mn0;
        l1 = l1 * al1 + sum1; m1 = mn1;
#pragma unroll
        for (int nf = 0; nf < 8; nf++) {
            o[nf][0] *= al0; o[nf][1] *= al0;
            o[nf][2] *= al1; o[nf][3] *= al1;
        }

        // ---- O += (Ph+Pl) V ----
#pragma unroll
        for (int kf = 0; kf < 4; kf++) {
            uint32_t ph[4], pl[4];
            pack_hl16(s[2 * kf][0],     s[2 * kf][1],     ph[0], pl[0]);
            pack_hl16(s[2 * kf][2],     s[2 * kf][3],     ph[1], pl[1]);
            pack_hl16(s[2 * kf + 1][0], s[2 * kf + 1][1], ph[2], pl[2]);
            pack_hl16(s[2 * kf + 1][2], s[2 * kf + 1][3], ph[3], pl[3]);
#pragma unroll
            for (int nf = 0; nf < 8; nf++) {
                uint32_t v0, v1;
                const int vrow = kf * 16 + lh * 8 + l8;
                ldsm_x2_t(v0, v1, stg + KVTILE + (uint32_t)(vrow * 128)
                          + (uint32_t)(((nf ^ l8)) << 4));
                mma_f16(o[nf], ph[0], ph[1], ph[2], ph[3], v0, v1);
                mma_f16(o[nf], pl[0], pl[1], pl[2], pl[3], v0, v1);
            }
        }

        if (c + 1 < NC) cp_wait<0>();
        __syncthreads();
    }

    // ---- normalize and write fp16 hi/lo ----
    const float inv0 = 1.0f / l0;
    const float inv1 = 1.0f / l1;
    const int row0 = qt * 128 + wid * 16 + g;
#pragma unroll
    for (int nf = 0; nf < 8; nf++) {
        const int col = h * DD + nf * 8 + 2 * t4;
        const size_t a0 = (size_t)(b * NN + row0) * CDIM + col;
        const size_t a1 = (size_t)(b * NN + row0 + 8) * CDIM + col;
        uint32_t h0, lo0, h1, lo1;
        pack_hl16(o[nf][0] * inv0, o[nf][1] * inv0, h0, lo0);
        pack_hl16(o[nf][2] * inv1, o[nf][3] * inv1, h1, lo1);
        *(uint32_t*)&Oh[a0] = h0; *(uint32_t*)&Ol[a0] = lo0;
        *(uint32_t*)&Oh[a1] = h1; *(uint32_t*)&Ol[a1] = lo1;
    }
#undef ISSUE_KV
}

// ---------------------------------------------------------------------------
// Launch
// ---------------------------------------------------------------------------
extern "C" void kernel_launch(void* const* d_in, const int* in_sizes, int n_in,
                              void* d_out, int out_size)
{
    const float* x  = (const float*)d_in[0];
    const float* y  = (const float*)d_in[1];
    const float* Wq = (const float*)d_in[2];
    const float* Wk = (const float*)d_in[3];
    const float* Wv = (const float*)d_in[4];
    const float* Wp = (const float*)d_in[5];
    const float* bp = (const float*)d_in[6];
    float* out = (float*)d_out;

    __half *xh, *xl, *yh, *yl, *w, *qh, *ql, *k1, *v1, *aoh, *aol;
    float* po;
    cudaGetSymbolAddress((void**)&xh, g_xh);   cudaGetSymbolAddress((void**)&xl, g_xl);
    cudaGetSymbolAddress((void**)&yh, g_yh);   cudaGetSymbolAddress((void**)&yl, g_yl);
    cudaGetSymbolAddress((void**)&w,  g_w);
    cudaGetSymbolAddress((void**)&qh, g_qh);   cudaGetSymbolAddress((void**)&ql, g_ql);
    cudaGetSymbolAddress((void**)&k1, g_k1);   cudaGetSymbolAddress((void**)&v1, g_v1);
    cudaGetSymbolAddress((void**)&aoh, g_aoh); cudaGetSymbolAddress((void**)&aol, g_aol);
    cudaGetSymbolAddress((void**)&po, g_po);

    cudaFuncSetAttribute(proj_fused,  cudaFuncAttributeMaxDynamicSharedMemorySize, GEMM_SMEM);
    cudaFuncSetAttribute(gemm_out_sk, cudaFuncAttributeMaxDynamicSharedMemorySize, GEMM_SMEM);
    cudaFuncSetAttribute(attn_mma,    cudaFuncAttributeMaxDynamicSharedMemorySize, ATTN_SMEM);

    float* p0 = po;
    float* p1 = po + BB * NN * CDIM;

    // 1. Fused convert
    convert_all<<<(TOT4 + 255) / 256, 256>>>(x, y, Wq, Wk, Wv, Wp,
                                             xh, xl, yh, yl, w);

    // 2. Fused Q/K/V projections
    proj_fused<<<dim3(CDIM / 128, (BB * LLEN) / 128, 3), 256, GEMM_SMEM>>>(
        xh, xl, yh, yl, w, qh, ql, k1, v1);

    // 3. Flash attention (fp16 2-term) -> fp16 hi/lo
    attn_mma<<<dim3(NN / 128, HH, BB), 256, ATTN_SMEM>>>(
        aoh, aol, qh, ql, k1, v1);

    // 4. Output projection, split-K=2
    gemm_out_sk<<<dim3(CDIM / 128, (BB * NN) / 128, 2), 256, GEMM_SMEM>>>(
        p0, p1, aoh, aol, w + 3 * (size_t)CDIM * CDIM);

    // 5. Merge partials + bias
    merge_out<<<((BB * NN * CDIM / 4) + 255) / 256, 256>>>(out, p0, p1, bp);
}

// round 13
// speedup vs baseline: 2.4330x; 1.2125x over previous
#include <cuda_runtime.h>
#include <cuda_fp16.h>
#include <math.h>
#include <stdint.h>

// Problem shape (fixed by the dataset)
#define BB   2
#define NN   1024
#define LLEN 4096
#define CDIM 1024
#define HH   16
#define DD   64

// ---------------- scratch (device globals; no allocs allowed) ---------------
__device__ __half g_xh[BB * NN * CDIM],   g_xl[BB * NN * CDIM];
__device__ __half g_y1[BB * LLEN * CDIM];                  // single fp16
__device__ __half g_w[4 * CDIM * CDIM];                    // single fp16 weights
__device__ __half g_qh[BB * NN * CDIM],   g_ql[BB * NN * CDIM];   // pre-scaled 0.125
__device__ __half g_k1[BB * LLEN * CDIM];                  // single fp16
__device__ __half g_v1[BB * LLEN * CDIM];                  // single fp16
__device__ __half g_ao[BB * NN * CDIM];                    // single fp16
__device__ float  g_po[2][BB * NN * CDIM];                 // split-K partials

extern __shared__ char dsm[];

// ---------------------------------------------------------------------------
// helpers
// ---------------------------------------------------------------------------
static __device__ __forceinline__ uint32_t smem_u32(const void* p) {
    uint32_t a;
    asm("{ .reg .u64 t; cvta.to.shared.u64 t, %1; cvt.u32.u64 %0, t; }"
        : "=r"(a) : "l"(p));
    return a;
}
static __device__ __forceinline__ void cp16(uint32_t dst, const void* src) {
    asm volatile("cp.async.cg.shared.global [%0], [%1], 16;"
                 :: "r"(dst), "l"(src));
}
static __device__ __forceinline__ void cp_commit() {
    asm volatile("cp.async.commit_group;" ::: "memory");
}
template <int N_>
static __device__ __forceinline__ void cp_wait() {
    asm volatile("cp.async.wait_group %0;" :: "n"(N_) : "memory");
}
static __device__ __forceinline__ void mma_f16(
    float* c, uint32_t a0, uint32_t a1, uint32_t a2, uint32_t a3,
    uint32_t b0, uint32_t b1)
{
    asm volatile(
        "mma.sync.aligned.m16n8k16.row.col.f32.f16.f16.f32 "
        "{%0,%1,%2,%3}, {%4,%5,%6,%7}, {%8,%9}, {%0,%1,%2,%3};"
        : "+f"(c[0]), "+f"(c[1]), "+f"(c[2]), "+f"(c[3])
        : "r"(a0), "r"(a1), "r"(a2), "r"(a3), "r"(b0), "r"(b1));
}
static __device__ __forceinline__ void ldsm_x4(uint32_t* r, uint32_t addr) {
    asm volatile("ldmatrix.sync.aligned.m8n8.x4.shared.b16 {%0,%1,%2,%3}, [%4];"
                 : "=r"(r[0]), "=r"(r[1]), "=r"(r[2]), "=r"(r[3]) : "r"(addr));
}
static __device__ __forceinline__ void ldsm_x2_t(uint32_t& r0, uint32_t& r1, uint32_t addr) {
    asm volatile("ldmatrix.sync.aligned.m8n8.x2.trans.shared.b16 {%0,%1}, [%2];"
                 : "=r"(r0), "=r"(r1) : "r"(addr));
}
static __device__ __forceinline__ void pack_hl16(
    float a, float b, uint32_t& hi, uint32_t& lo)
{
    __half2 h = __floats2half2_rn(a, b);
    __half2 l = __floats2half2_rn(a - __half2float(__low2half(h)),
                                  b - __half2float(__high2half(h)));
    hi = *(uint32_t*)&h;
    lo = *(uint32_t*)&l;
}

// ---------------------------------------------------------------------------
// fused convert: x -> fp16 hi/lo;  y, Wq..Wp -> single fp16.  ONE launch.
// ---------------------------------------------------------------------------
#define X4 ((BB * NN * CDIM) / 4)
#define Y4 ((BB * LLEN * CDIM) / 4)
#define W4 ((CDIM * CDIM) / 4)
#define TOT4 (X4 + Y4 + 4 * W4)

__global__ void convert_all(const float* __restrict__ x, const float* __restrict__ y,
                            const float* __restrict__ Wq, const float* __restrict__ Wk,
                            const float* __restrict__ Wv, const float* __restrict__ Wp,
                            __half* __restrict__ xh, __half* __restrict__ xl,
                            __half* __restrict__ y1, __half* __restrict__ w)
{
    const int i = blockIdx.x * blockDim.x + threadIdx.x;
    if (i >= TOT4) return;

    if (i < X4) {        // hi/lo split for x
        float4 v = ((const float4*)x)[i];
        uint32_t h0, l0, h1, l1;
        pack_hl16(v.x, v.y, h0, l0);
        pack_hl16(v.z, v.w, h1, l1);
        ((uint32_t*)xh)[i * 2 + 0] = h0;
        ((uint32_t*)xh)[i * 2 + 1] = h1;
        ((uint32_t*)xl)[i * 2 + 0] = l0;
        ((uint32_t*)xl)[i * 2 + 1] = l1;
    } else {             // single fp16 for y and weights
        const float* src; __half* dst; int j;
        int r = i - X4;
        if (r < Y4) { src = y; dst = y1; j = r; }
        else {
            r -= Y4;
            const int wsel = r / W4;
            j = r - wsel * W4;
            src = (wsel == 0) ? Wq : (wsel == 1) ? Wk : (wsel == 2) ? Wv : Wp;
            dst = w + (size_t)wsel * CDIM * CDIM;
        }
        float4 v = ((const float4*)src)[j];
        __half2 a = __floats2half2_rn(v.x, v.y);
        __half2 b = __floats2half2_rn(v.z, v.w);
        ((uint32_t*)dst)[j * 2 + 0] = *(uint32_t*)&a;
        ((uint32_t*)dst)[j * 2 + 1] = *(uint32_t*)&b;
    }
}

// ---------------------------------------------------------------------------
// GEMM body, fp16.  TWOA: C = (Ah+Al)*B^T, else C = Ah*B^T.
// BK=64, tile 128x128, 256 thr.  Smem row 128B, swizzle s^(r&7).
// omode: 0 = fp32 C, 1 = fp16 hi/lo (*oscale), 2 = fp16 single.
// ---------------------------------------------------------------------------
#define GTILE  16384
#define GEMM_SMEM (2 * 3 * GTILE)      // worst case (TWOA): 98304

#define LOAD_STAGE(cc, buf) do {                                              \
        const uint32_t bo = (uint32_t)(buf) * STB;                            \
        _Pragma("unroll")                                                     \
        for (int k = 0; k < 4; k++) {                                         \
            const int j   = tid + k * 256;                                    \
            const int row = j >> 3;                                           \
            const int s   = j & 7;                                            \
            const uint32_t doff = (uint32_t)(row * 128 + (((s) ^ (row & 7)) << 4)); \
            cp16(sb + bo + doff, Ah + (size_t)(m0 + row) * K + (cc) * 64 + s * 8); \
            if (TWOA)                                                         \
                cp16(sb + bo + GTILE + doff, Al + (size_t)(m0 + row) * K + (cc) * 64 + s * 8); \
            cp16(sb + bo + BOF + doff, Bs + (size_t)(n0 + row) * K + (cc) * 64 + s * 8); \
        }                                                                     \
    } while (0)

template <bool TWOA>
static __device__ __forceinline__ void gemm_body(
    float* __restrict__ C,
    __half* __restrict__ Ch, __half* __restrict__ Cl, __half* __restrict__ Cs,
    const __half* __restrict__ Ah, const __half* __restrict__ Al,
    const __half* __restrict__ Bs,
    float oscale, int omode, int N, int K, int bx, int by, int c0, int c1)
{
    constexpr uint32_t STB = TWOA ? 3 * GTILE : 2 * GTILE;
    constexpr uint32_t BOF = TWOA ? 2 * GTILE : GTILE;

    const int tid  = threadIdx.x;
    const int wid  = tid >> 5;
    const int lane = tid & 31;
    const int wm   = wid & 3;
    const int wn   = wid >> 2;
    const int g    = lane >> 2;
    const int t4   = lane & 3;
    const int m0   = by * 128;
    const int n0   = bx * 128;
    const int r15  = lane & 15;
    const int hi8  = lane >> 4;
    const int r7   = r15 & 7;

    const uint32_t sb = smem_u32(dsm);

    float acc[2][8][4];
#pragma unroll
    for (int mf = 0; mf < 2; mf++)
#pragma unroll
        for (int nf = 0; nf < 8; nf++)
#pragma unroll
            for (int j = 0; j < 4; j++) acc[mf][nf][j] = 0.0f;

    LOAD_STAGE(c0, 0);
    cp_commit();

    for (int c = c0; c < c1; c++) {
        const int buf = (c - c0) & 1;
        if (c + 1 < c1) {
            LOAD_STAGE(c + 1, buf ^ 1);
            cp_commit();
            cp_wait<1>();
        } else {
            cp_wait<0>();
        }
        __syncthreads();

        const uint32_t stg = sb + (uint32_t)buf * STB;

#pragma unroll
        for (int ks = 0; ks < 4; ks++) {
            const uint32_t sx = (uint32_t)((((2 * ks + hi8) ^ r7)) << 4);
            uint32_t ah[2][4], al[2][4];
#pragma unroll
            for (int mf = 0; mf < 2; mf++) {
                const uint32_t ra = (uint32_t)((wm * 32 + mf * 16 + r15) * 128) + sx;
                ldsm_x4(ah[mf], stg + ra);
                if (TWOA) ldsm_x4(al[mf], stg + GTILE + ra);
            }
#pragma unroll
            for (int nfp = 0; nfp < 4; nfp++) {
                uint32_t b4[4];
                ldsm_x4(b4, stg + BOF +
                        (uint32_t)((wn * 64 + nfp * 16 + r15) * 128) + sx);
#pragma unroll
                for (int mf = 0; mf < 2; mf++) {
                    float* cc0 = acc[mf][2 * nfp];
                    float* cc1 = acc[mf][2 * nfp + 1];
                    mma_f16(cc0, ah[mf][0], ah[mf][1], ah[mf][2], ah[mf][3], b4[0], b4[2]);
                    mma_f16(cc1, ah[mf][0], ah[mf][1], ah[mf][2], ah[mf][3], b4[1], b4[3]);
                    if (TWOA) {
                        mma_f16(cc0, al[mf][0], al[mf][1], al[mf][2], al[mf][3], b4[0], b4[2]);
                        mma_f16(cc1, al[mf][0], al[mf][1], al[mf][2], al[mf][3], b4[1], b4[3]);
                    }
                }
            }
        }
        __syncthreads();
    }

#pragma unroll
    for (int mf = 0; mf < 2; mf++) {
        const int row = m0 + wm * 32 + mf * 16 + g;
#pragma unroll
        for (int nf = 0; nf < 8; nf++) {
            const int col = n0 + wn * 64 + nf * 8 + 2 * t4;
            if (omode == 0) {
                float2 v0, v1;
                v0.x = acc[mf][nf][0]; v0.y = acc[mf][nf][1];
                v1.x = acc[mf][nf][2]; v1.y = acc[mf][nf][3];
                *(float2*)&C[(size_t)row * N + col]       = v0;
                *(float2*)&C[(size_t)(row + 8) * N + col] = v1;
            } else if (omode == 1) {
                uint32_t h0, l0, h1, l1;
                pack_hl16(acc[mf][nf][0] * oscale, acc[mf][nf][1] * oscale, h0, l0);
                pack_hl16(acc[mf][nf][2] * oscale, acc[mf][nf][3] * oscale, h1, l1);
                *(uint32_t*)&Ch[(size_t)row * N + col]       = h0;
                *(uint32_t*)&Cl[(size_t)row * N + col]       = l0;
                *(uint32_t*)&Ch[(size_t)(row + 8) * N + col] = h1;
                *(uint32_t*)&Cl[(size_t)(row + 8) * N + col] = l1;
            } else {
                __half2 v0 = __floats2half2_rn(acc[mf][nf][0], acc[mf][nf][1]);
                __half2 v1 = __floats2half2_rn(acc[mf][nf][2], acc[mf][nf][3]);
                *(uint32_t*)&Cs[(size_t)row * N + col]       = *(uint32_t*)&v0;
                *(uint32_t*)&Cs[(size_t)(row + 8) * N + col] = *(uint32_t*)&v1;
            }
        }
    }
}

// Fused Q/K/V projection (z = 0: Q 2-term A + hi/lo out; 1,2: K/V single)
__global__ __launch_bounds__(256, 2)
void proj_fused(const __half* __restrict__ xh, const __half* __restrict__ xl,
                const __half* __restrict__ y1, const __half* __restrict__ w,
                __half* __restrict__ qh, __half* __restrict__ ql,
                __half* __restrict__ k1, __half* __restrict__ v1)
{
    const int z = blockIdx.z;
    if (z == 0 && blockIdx.y >= (BB * NN) / 128) return;

    const __half* Bs = w + (size_t)z * CDIM * CDIM;
    if (z == 0)
        gemm_body<true>(nullptr, qh, ql, nullptr, xh, xl, Bs, 0.125f, 1,
                        CDIM, CDIM, blockIdx.x, blockIdx.y, 0, CDIM >> 6);
    else
        gemm_body<false>(nullptr, nullptr, nullptr, (z == 1) ? k1 : v1,
                         y1, nullptr, Bs, 1.0f, 2,
                         CDIM, CDIM, blockIdx.x, blockIdx.y, 0, CDIM >> 6);
}

// Output projection, split-K=2, single-term A
__global__ __launch_bounds__(256, 2)
void gemm_out_sk(float* __restrict__ P0, float* __restrict__ P1,
                 const __half* __restrict__ A1, const __half* __restrict__ Bs)
{
    const int z = blockIdx.z;
    const int half = (CDIM >> 6) / 2;
    gemm_body<false>(z ? P1 : P0, nullptr, nullptr, nullptr, A1, nullptr, Bs,
                     1.0f, 0, CDIM, CDIM, blockIdx.x, blockIdx.y,
                     z * half, (z + 1) * half);
}

// merge: out = p0 + p1 + bias
__global__ void merge_out(float* __restrict__ out,
                          const float* __restrict__ p0, const float* __restrict__ p1,
                          const float* __restrict__ bias)
{
    const int i = blockIdx.x * blockDim.x + threadIdx.x;
    if (i >= (BB * NN * CDIM) / 4) return;
    const int col4 = i & (CDIM / 4 - 1);
    float4 a = ((const float4*)p0)[i];
    float4 b = ((const float4*)p1)[i];
    float4 bb = ((const float4*)bias)[col4];
    float4 o;
    o.x = a.x + b.x + bb.x; o.y = a.y + b.y + bb.y;
    o.z = a.z + b.z + bb.z; o.w = a.w + b.w + bb.w;
    ((float4*)out)[i] = o;
}

// ---------------------------------------------------------------------------
// Flash attention, fp16 2-term interior, single fp16 output.
// CTA = 128 queries of one (b,h); 8 warps x 16 rows, warp-local softmax.
// Q (hi/lo) persistent in smem; K, V single fp16, double-buffered.
// ---------------------------------------------------------------------------
#define QSM_B   32768
#define KVTILE  8192
#define ASTAGE_B (2 * KVTILE)
#define ATTN_SMEM (QSM_B + 2 * ASTAGE_B)   // 65536

__global__ __launch_bounds__(256, 2)
void attn_mma(__half* __restrict__ O1,
              const __half* __restrict__ Qh, const __half* __restrict__ Ql,
              const __half* __restrict__ K1, const __half* __restrict__ V1)
{
    const int tid  = threadIdx.x;
    const int wid  = tid >> 5;
    const int lane = tid & 31;
    const int g    = lane >> 2;
    const int t4   = lane & 3;
    const int r15  = lane & 15;
    const int hi8  = lane >> 4;
    const int r7   = r15 & 7;
    const int l8   = lane & 7;
    const int lh   = (lane >> 3) & 1;
    const int qt   = blockIdx.x;
    const int h    = blockIdx.y;
    const int b    = blockIdx.z;
    const uint32_t sb = smem_u32(dsm);

    {
#pragma unroll
        for (int k = 0; k < 8; k++) {
            const int j   = tid + k * 256;
            const int hs  = j >> 10;
            const int rem = j & 1023;
            const int row = rem >> 3;
            const int s   = rem & 7;
            const __half* src = (hs ? Ql : Qh) +
                ((size_t)(b * NN + qt * 128 + row) * CDIM + h * DD + s * 8);
            cp16(sb + hs * 16384 + row * 128 + ((s ^ (row & 7)) << 4), src);
        }
        cp_commit();
    }

    const size_t kbase = (size_t)b * LLEN * CDIM + h * DD;

#define ISSUE_KV(cc, buf) do {                                                \
        _Pragma("unroll")                                                     \
        for (int k = 0; k < 4; k++) {                                         \
            const int j    = tid + k * 256;                                   \
            const int tile = j >> 9;                                          \
            const int rem  = j & 511;                                         \
            const int row  = rem >> 3;                                        \
            const int s    = rem & 7;                                         \
            const __half* src = (tile ? V1 : K1) + kbase +                    \
                (size_t)((cc) * 64 + row) * CDIM + s * 8;                     \
            cp16(sb + QSM_B + (buf) * ASTAGE_B + tile * KVTILE                \
                 + row * 128 + ((s ^ (row & 7)) << 4), src);                  \
        }                                                                     \
    } while (0)

    float m0 = -1e30f, m1 = -1e30f, l0 = 0.0f, l1 = 0.0f;
    float o[8][4];
#pragma unroll
    for (int nf = 0; nf < 8; nf++)
#pragma unroll
        for (int j = 0; j < 4; j++) o[nf][j] = 0.0f;

    ISSUE_KV(0, 0); cp_commit();
    cp_wait<0>(); __syncthreads();

    const uint32_t qrow = (uint32_t)((wid * 16 + r15) * 128);

    const int NC = LLEN / 64;
    for (int c = 0; c < NC; c++) {
        const int buf = c & 1;
        if (c + 1 < NC) { ISSUE_KV(c + 1, buf ^ 1); cp_commit(); }

        const uint32_t stg = sb + QSM_B + buf * ASTAGE_B;

        float s[8][4];
#pragma unroll
        for (int nf = 0; nf < 8; nf++)
#pragma unroll
            for (int j = 0; j < 4; j++) s[nf][j] = 0.0f;

#pragma unroll
        for (int kf = 0; kf < 4; kf++) {
            const uint32_t sx = (uint32_t)((((2 * kf + hi8) ^ r7)) << 4);
            uint32_t qh4[4], ql4[4];
            ldsm_x4(qh4, sb + qrow + sx);
            ldsm_x4(ql4, sb + 16384 + qrow + sx);
#pragma unroll
            for (int nfp = 0; nfp < 4; nfp++) {
                uint32_t k4[4];
                ldsm_x4(k4, stg + (uint32_t)((nfp * 16 + r15) * 128) + sx);
                float* s0 = s[2 * nfp];
                float* s1 = s[2 * nfp + 1];
                mma_f16(s0, qh4[0], qh4[1], qh4[2], qh4[3], k4[0], k4[2]);
                mma_f16(s0, ql4[0], ql4[1], ql4[2], ql4[3], k4[0], k4[2]);
                mma_f16(s1, qh4[0], qh4[1], qh4[2], qh4[3], k4[1], k4[3]);
                mma_f16(s1, ql4[0], ql4[1], ql4[2], ql4[3], k4[1], k4[3]);
            }
        }

        float cm0 = -1e30f, cm1 = -1e30f;
#pragma unroll
        for (int nf = 0; nf < 8; nf++) {
            cm0 = fmaxf(cm0, fmaxf(s[nf][0], s[nf][1]));
            cm1 = fmaxf(cm1, fmaxf(s[nf][2], s[nf][3]));
        }
        cm0 = fmaxf(cm0, __shfl_xor_sync(0xFFFFFFFFu, cm0, 1));
        cm0 = fmaxf(cm0, __shfl_xor_sync(0xFFFFFFFFu, cm0, 2));
        cm1 = fmaxf(cm1, __shfl_xor_sync(0xFFFFFFFFu, cm1, 1));
        cm1 = fmaxf(cm1, __shfl_xor_sync(0xFFFFFFFFu, cm1, 2));
        const float mn0 = fmaxf(m0, cm0);
        const float mn1 = fmaxf(m1, cm1);
        const float al0 = __expf(m0 - mn0);
        const float al1 = __expf(m1 - mn1);
        float sum0 = 0.0f, sum1 = 0.0f;
#pragma unroll
        for (int nf = 0; nf < 8; nf++) {
            s[nf][0] = __expf(s[nf][0] - mn0); sum0 += s[nf][0];
            s[nf][1] = __expf(s[nf][1] - mn0); sum0 += s[nf][1];
            s[nf][2] = __expf(s[nf][2] - mn1); sum1 += s[nf][2];
            s[nf][3] = __expf(s[nf][3] - mn1); sum1 += s[nf][3];
        }
        sum0 += __shfl_xor_sync(0xFFFFFFFFu, sum0, 1);
        sum0 += __shfl_xor_sync(0xFFFFFFFFu, sum0, 2);
        sum1 += __shfl_xor_sync(0xFFFFFFFFu, sum1, 1);
        sum1 += __shfl_xor_sync(0xFFFFFFFFu, sum1, 2);
        l0 = l0 * al0 + sum0; m0 = mn0;
        l1 = l1 * al1 + sum1; m1 = mn1;
#pragma unroll
        for (int nf = 0; nf < 8; nf++) {
            o[nf][0] *= al0; o[nf][1] *= al0;
            o[nf][2] *= al1; o[nf][3] *= al1;
        }

#pragma unroll
        for (int kf = 0; kf < 4; kf++) {
            uint32_t ph[4], pl[4];
            pack_hl16(s[2 * kf][0],     s[2 * kf][1],     ph[0], pl[0]);
            pack_hl16(s[2 * kf][2],     s[2 * kf][3],     ph[1], pl[1]);
            pack_hl16(s[2 * kf + 1][0], s[2 * kf + 1][1], ph[2], pl[2]);
            pack_hl16(s[2 * kf + 1][2], s[2 * kf + 1][3], ph[3], pl[3]);
#pragma unroll
            for (int nf = 0; nf < 8; nf++) {
                uint32_t v0, v1;
                const int vrow = kf * 16 + lh * 8 + l8;
                ldsm_x2_t(v0, v1, stg + KVTILE + (uint32_t)(vrow * 128)
                          + (uint32_t)(((nf ^ l8)) << 4));
                mma_f16(o[nf], ph[0], ph[1], ph[2], ph[3], v0, v1);
                mma_f16(o[nf], pl[0], pl[1], pl[2], pl[3], v0, v1);
            }
        }

        if (c + 1 < NC) cp_wait<0>();
        __syncthreads();
    }

    // ---- normalize and write single fp16 ----
    const float inv0 = 1.0f / l0;
    const float inv1 = 1.0f / l1;
    const int row0 = qt * 128 + wid * 16 + g;
#pragma unroll
    for (int nf = 0; nf < 8; nf++) {
        const int col = h * DD + nf * 8 + 2 * t4;
        const size_t a0 = (size_t)(b * NN + row0) * CDIM + col;
        const size_t a1 = (size_t)(b * NN + row0 + 8) * CDIM + col;
        __half2 v0 = __floats2half2_rn(o[nf][0] * inv0, o[nf][1] * inv0);
        __half2 v1 = __floats2half2_rn(o[nf][2] * inv1, o[nf][3] * inv1);
        *(uint32_t*)&O1[a0] = *(uint32_t*)&v0;
        *(uint32_t*)&O1[a1] = *(uint32_t*)&v1;
    }
#undef ISSUE_KV
}

// ---------------------------------------------------------------------------
// Launch
// ---------------------------------------------------------------------------
extern "C" void kernel_launch(void* const* d_in, const int* in_sizes, int n_in,
                              void* d_out, int out_size)
{
    const float* x  = (const float*)d_in[0];
    const float* y  = (const float*)d_in[1];
    const float* Wq = (const float*)d_in[2];
    const float* Wk = (const float*)d_in[3];
    const float* Wv = (const float*)d_in[4];
    const float* Wp = (const float*)d_in[5];
    const float* bp = (const float*)d_in[6];
    float* out = (float*)d_out;

    __half *xh, *xl, *y1, *w, *qh, *ql, *k1, *v1, *ao;
    float* po;
    cudaGetSymbolAddress((void**)&xh, g_xh);   cudaGetSymbolAddress((void**)&xl, g_xl);
    cudaGetSymbolAddress((void**)&y1, g_y1);
    cudaGetSymbolAddress((void**)&w,  g_w);
    cudaGetSymbolAddress((void**)&qh, g_qh);   cudaGetSymbolAddress((void**)&ql, g_ql);
    cudaGetSymbolAddress((void**)&k1, g_k1);   cudaGetSymbolAddress((void**)&v1, g_v1);
    cudaGetSymbolAddress((void**)&ao, g_ao);
    cudaGetSymbolAddress((void**)&po, g_po);

    cudaFuncSetAttribute(proj_fused,  cudaFuncAttributeMaxDynamicSharedMemorySize, GEMM_SMEM);
    cudaFuncSetAttribute(gemm_out_sk, cudaFuncAttributeMaxDynamicSharedMemorySize, 2 * 2 * GTILE);
    cudaFuncSetAttribute(attn_mma,    cudaFuncAttributeMaxDynamicSharedMemorySize, ATTN_SMEM);

    float* p0 = po;
    float* p1 = po + BB * NN * CDIM;

    // 1. Fused convert
    convert_all<<<(TOT4 + 255) / 256, 256>>>(x, y, Wq, Wk, Wv, Wp, xh, xl, y1, w);

    // 2. Fused Q/K/V projections
    proj_fused<<<dim3(CDIM / 128, (BB * LLEN) / 128, 3), 256, GEMM_SMEM>>>(
        xh, xl, y1, w, qh, ql, k1, v1);

    // 3. Flash attention -> single fp16
    attn_mma<<<dim3(NN / 128, HH, BB), 256, ATTN_SMEM>>>(ao, qh, ql, k1, v1);

    // 4. Output projection, split-K=2 (single-term A)
    gemm_out_sk<<<dim3(CDIM / 128, (BB * NN) / 128, 2), 256, 2 * 2 * GTILE>>>(
        p0, p1, ao, w + 3 * (size_t)CDIM * CDIM);

    // 5. Merge partials + bias
    merge_out<<<((BB * NN * CDIM / 4) + 255) / 256, 256>>>(out, p0, p1, bp);
}